// round 14
// baseline (speedup 1.0000x reference)
#include <cuda_runtime.h>
#include <cuda_fp16.h>
#include <math.h>
#include <stdint.h>

// Problem constants
#define Bc   8
#define Sc   1024
#define Ec   512
#define Hc   8
#define HDc  64
#define Pc   32
#define Nt   (Bc*Sc)     // 8192 tokens
#define HIDc 2048

// ---------------- scratch (device globals; allocation-free) ----------------
__device__ float g_offraw[Nt*Hc*Pc];   // fp32: feeds index rounding
__device__ float g_x1[Nt*Ec];          // fp32: dominant residual for LN2
__device__ float g_bqkv[1536];         // packed dq|dk|dv bias
__device__ int   g_sp[Nt*Pc];
__device__ int   g_vl[Bc];

// fp16 activation/operand buffers
#define WTOT 5636096
__device__ __half h_x[Nt*Ec];
__device__ __half h_w[WTOT];
__device__ __half h_qkv[Nt*3*Ec];
__device__ __half h_lo[Nt*Ec];
__device__ __half h_local[Nt*Ec];
__device__ __half h_long[Nt*Ec];
__device__ __half h_h1[Nt*Ec];
__device__ __half h_qkvd[Nt*3*Ec];     // dq|dk|dv packed, stride 1536
__device__ __half h_lattn[Nt*Ec];
__device__ __half h_gh[Nt*Ec];
__device__ __half h_gate[Nt*Ec];
__device__ __half h_x1[Nt*Ec];
__device__ __half h_ffnh[Nt*HIDc];
__device__ __half h_f[Nt*Ec];

// weight offsets in h_w (halves); W_DQ..W_DV contiguous => packed [1536,512]
#define W_INPROJ 0
#define W_MHA    786432
#define W_DQ     1048576
#define W_DK     1310720
#define W_DV     1572864
#define W_DO     1835008
#define W_OFF1   2097152
#define W_OFF2   2359296
#define W_GATE1  2490368
#define W_GATE2  3276800
#define W_FFN1   3538944
#define W_FFN2   4587520

// smem: ktile32, 4 slabs/buffer, slab stride 130 uint4 (conflict-free)
#define SLAB_STRIDE 130
#define BUF_U4      (4*SLAB_STRIDE)   // 520 uint4 per matrix per buffer

// ---------------- helpers -----------------------------------------------------
__device__ __forceinline__ void mma_f16(float4& d, const uint32_t* a, const uint32_t* b) {
    asm volatile(
        "mma.sync.aligned.m16n8k16.row.col.f32.f16.f16.f32 "
        "{%0,%1,%2,%3}, {%4,%5,%6,%7}, {%8,%9}, {%0,%1,%2,%3};"
        : "+f"(d.x), "+f"(d.y), "+f"(d.z), "+f"(d.w)
        : "r"(a[0]), "r"(a[1]), "r"(a[2]), "r"(a[3]),
          "r"(b[0]), "r"(b[1]));
}

__device__ __forceinline__ void ldsm_x4(uint32_t& r0, uint32_t& r1, uint32_t& r2, uint32_t& r3, uint32_t a) {
    asm volatile("ldmatrix.sync.aligned.m8n8.x4.shared.b16 {%0,%1,%2,%3}, [%4];"
        : "=r"(r0), "=r"(r1), "=r"(r2), "=r"(r3) : "r"(a));
}

__device__ __forceinline__ void cpa16ca(uint32_t dst, const void* src) {
    asm volatile("cp.async.ca.shared.global [%0], [%1], 16;" :: "r"(dst), "l"(src));
}
#define CPA_COMMIT()  asm volatile("cp.async.commit_group;" ::: "memory")
#define CPA_WAIT0()   asm volatile("cp.async.wait_group 0;" ::: "memory")

__device__ __forceinline__ float apply_epi(float v, int EPI) {
    if (EPI == 1)      return 0.5f * v * (1.f + erff(v * 0.70710678118654752f));
    else if (EPI == 2) return tanhf(v);
    else if (EPI == 3) return 1.f / (1.f + expf(-v));
    return v;
}

__device__ __forceinline__ float dot8h(uint4 a, uint4 b) {
    const __half2* pa = reinterpret_cast<const __half2*>(&a);
    const __half2* pb = reinterpret_cast<const __half2*>(&b);
    float s = 0.f;
#pragma unroll
    for (int i = 0; i < 4; i++) {
        float2 fa = __half22float2(pa[i]);
        float2 fb = __half22float2(pb[i]);
        s += fa.x*fb.x + fa.y*fb.y;
    }
    return s;
}

// ---------------- fp32 -> fp16 conversion (x + 13 weights, one launch) --------
__global__ void cvt_all_kernel(
    const float* x,
    const float* w_inproj, const float* w_mha,
    const float* w_dq, const float* w_dk, const float* w_dv, const float* w_do,
    const float* w_off1, const float* w_off2,
    const float* w_gate1, const float* w_gate2,
    const float* w_ffn1, const float* w_ffn2)
{
    int g = blockIdx.x * blockDim.x + threadIdx.x;   // float4 index
    const float* src; __half* dst; int li;
    if      (g < 1048576) { src = x;        dst = h_x;            li = g;           }
    else if (g < 1245184) { src = w_inproj; dst = h_w + W_INPROJ; li = g - 1048576; }
    else if (g < 1310720) { src = w_mha;    dst = h_w + W_MHA;    li = g - 1245184; }
    else if (g < 1376256) { src = w_dq;     dst = h_w + W_DQ;     li = g - 1310720; }
    else if (g < 1441792) { src = w_dk;     dst = h_w + W_DK;     li = g - 1376256; }
    else if (g < 1507328) { src = w_dv;     dst = h_w + W_DV;     li = g - 1441792; }
    else if (g < 1572864) { src = w_do;     dst = h_w + W_DO;     li = g - 1507328; }
    else if (g < 1638400) { src = w_off1;   dst = h_w + W_OFF1;   li = g - 1572864; }
    else if (g < 1671168) { src = w_off2;   dst = h_w + W_OFF2;   li = g - 1638400; }
    else if (g < 1867776) { src = w_gate1;  dst = h_w + W_GATE1;  li = g - 1671168; }
    else if (g < 1933312) { src = w_gate2;  dst = h_w + W_GATE2;  li = g - 1867776; }
    else if (g < 2195456) { src = w_ffn1;   dst = h_w + W_FFN1;   li = g - 1933312; }
    else                  { src = w_ffn2;   dst = h_w + W_FFN2;   li = g - 2195456; }

    float4 v = reinterpret_cast<const float4*>(src)[li];
    __half2 h0 = __floats2half2_rn(v.x, v.y);
    __half2 h1 = __floats2half2_rn(v.z, v.w);
    uint2 out = make_uint2(*reinterpret_cast<uint32_t*>(&h0), *reinterpret_cast<uint32_t*>(&h1));
    reinterpret_cast<uint2*>(dst)[li] = out;
}

// pack dq|dk|dv biases into one 1536 vector
__global__ void pack_bias_kernel(const float* dq_b, const float* dk_b, const float* dv_b)
{
    int i = blockIdx.x * blockDim.x + threadIdx.x;
    if (i >= 1536) return;
    float v;
    if (i < 512)       v = dq_b[i];
    else if (i < 1024) v = dk_b[i - 512];
    else               v = dv_b[i - 1024];
    g_bqkv[i] = v;
}

// ============================================================================
// FP16 GEMM: cp.async.ca double buffer (L1-allocating async copy) + ldmatrix.
// CTA 128x128, ktile 32, 8 warps. Threads 0-127 copy A, 128-255 copy B.
// One sync per ktile. EPI: 0 none,1 gelu,2 tanh,3 sigmoid. OUT: 0 fp32,1 fp16.
// M%128==0, N%128==0, K%32==0.
// ============================================================================
template<int EPI, int OUT>
__global__ __launch_bounds__(256, 2) void hgemm(
    const __half* __restrict__ A, const __half* __restrict__ Bw,
    const float* __restrict__ bias, float* __restrict__ C32,
    __half* __restrict__ C16, int M, int N, int K)
{
    __shared__ uint4 sA[2*BUF_U4];
    __shared__ uint4 sB[2*BUF_U4];

    const int t    = threadIdx.x;
    const int lane = t & 31;
    const int w    = t >> 5;
    const int wm   = w & 3;
    const int wn   = w >> 2;
    const long rowBase = (long)blockIdx.y * 128;
    const long colBase = (long)blockIdx.x * 128;

    float4 acc[2][8];
#pragma unroll
    for (int mt = 0; mt < 2; mt++)
#pragma unroll
        for (int nt = 0; nt < 8; nt++) acc[mt][nt] = make_float4(0.f,0.f,0.f,0.f);

    // copier role: half 0 -> A rows, half 1 -> B rows
    const int half = t >> 7;
    const int tt   = t & 127;
    const int kq   = tt & 3;          // slab 0..3
    const int r0   = tt >> 2;         // 0..31
    const __half* G = half ? (Bw + colBase * (long)K) : (A + rowBase * (long)K);
    const uint32_t dstBase = (uint32_t)__cvta_generic_to_shared(half ? sB : sA);

    // ldmatrix per-lane addresses (buffer 0)
    const uint32_t sAsh = (uint32_t)__cvta_generic_to_shared(sA);
    const uint32_t sBsh = (uint32_t)__cvta_generic_to_shared(sB);
    const int li  = lane & 7;
    const int grp = lane >> 3;
    uint32_t aAddr[2], bAddr[4];
#pragma unroll
    for (int mt = 0; mt < 2; mt++)
        aAddr[mt] = sAsh + (uint32_t)((((grp>>1)*SLAB_STRIDE) + wm*32 + mt*16 + (grp&1)*8 + li) * 16);
#pragma unroll
    for (int p = 0; p < 4; p++)
        bAddr[p] = sBsh + (uint32_t)((((grp&1)*SLAB_STRIDE) + wn*64 + p*16 + (grp>>1)*8 + li) * 16);

    auto issueTile = [&](int kt, int buf) {
#pragma unroll
        for (int i = 0; i < 4; i++)
            cpa16ca(dstBase + (uint32_t)((buf*BUF_U4 + kq*SLAB_STRIDE + r0 + 32*i) * 16),
                    G + (long)(r0 + 32*i) * K + kt + kq*8);
        CPA_COMMIT();
    };

    issueTile(0, 0);
    const int nT = K >> 5;
    int cur = 0;

    for (int ti = 0; ti < nT; ti++) {
        CPA_WAIT0();
        __syncthreads();
        if (ti + 1 < nT) issueTile((ti + 1) << 5, cur ^ 1);

        const uint32_t off = (uint32_t)(cur * BUF_U4 * 16);
#pragma unroll
        for (int s = 0; s < 2; s++) {
            const uint32_t soff = off + (uint32_t)(s * 2 * SLAB_STRIDE * 16);
            uint32_t af[2][4];
            uint32_t bf[8][2];
            ldsm_x4(af[0][0], af[0][1], af[0][2], af[0][3], aAddr[0] + soff);
            ldsm_x4(af[1][0], af[1][1], af[1][2], af[1][3], aAddr[1] + soff);
#pragma unroll
            for (int p = 0; p < 4; p++)
                ldsm_x4(bf[2*p][0], bf[2*p][1], bf[2*p+1][0], bf[2*p+1][1], bAddr[p] + soff);
#pragma unroll
            for (int mt = 0; mt < 2; mt++)
#pragma unroll
                for (int nt = 0; nt < 8; nt++)
                    mma_f16(acc[mt][nt], af[mt], bf[nt]);
        }
        cur ^= 1;
    }

    const int c2 = (lane & 3) * 2;
    const int q  = lane >> 2;
#pragma unroll
    for (int mt = 0; mt < 2; mt++) {
        long r0o = rowBase + wm*32 + mt*16 + q;
        long r1o = r0o + 8;
#pragma unroll
        for (int nt = 0; nt < 8; nt++) {
            int col = (int)colBase + wn*64 + nt*8 + c2;
            float b0 = bias[col], b1 = bias[col+1];
            float4 a = acc[mt][nt];
            float v0 = apply_epi(a.x + b0, EPI);
            float v1 = apply_epi(a.y + b1, EPI);
            float v2 = apply_epi(a.z + b0, EPI);
            float v3 = apply_epi(a.w + b1, EPI);
            if (OUT == 0) {
                *reinterpret_cast<float2*>(C32 + r0o * N + col) = make_float2(v0, v1);
                *reinterpret_cast<float2*>(C32 + r1o * N + col) = make_float2(v2, v3);
            } else {
                *reinterpret_cast<__half2*>(C16 + r0o * N + col) = __floats2half2_rn(v0, v1);
                *reinterpret_cast<__half2*>(C16 + r1o * N + col) = __floats2half2_rn(v2, v3);
            }
        }
    }
}

// ============================================================================
// gate1-specialized fp16 GEMM, same cp.async.ca pipeline per segment.
// ============================================================================
__global__ __launch_bounds__(256, 2) void hgemm_gate1(
    const __half* __restrict__ A0, const __half* __restrict__ A1,
    const __half* __restrict__ A2, const __half* __restrict__ Bw,
    const float* __restrict__ bias, __half* __restrict__ C16)
{
    __shared__ uint4 sA[2*BUF_U4];
    __shared__ uint4 sB[2*BUF_U4];

    const int t    = threadIdx.x;
    const int lane = t & 31;
    const int w    = t >> 5;
    const int wm   = w & 3;
    const int wn   = w >> 2;
    const long rowBase = (long)blockIdx.y * 128;
    const long colBase = (long)blockIdx.x * 128;
    const int  N = 512, K = 1536;

    float4 acc[2][8];
#pragma unroll
    for (int mt = 0; mt < 2; mt++)
#pragma unroll
        for (int nt = 0; nt < 8; nt++) acc[mt][nt] = make_float4(0.f,0.f,0.f,0.f);

    const int half = t >> 7;
    const int tt   = t & 127;
    const int kq   = tt & 3;
    const int r0   = tt >> 2;
    const uint32_t dstBase = (uint32_t)__cvta_generic_to_shared(half ? sB : sA);
    const long gstride = half ? (long)K : (long)Ec;

    const uint32_t sAsh = (uint32_t)__cvta_generic_to_shared(sA);
    const uint32_t sBsh = (uint32_t)__cvta_generic_to_shared(sB);
    const int li  = lane & 7;
    const int grp = lane >> 3;
    uint32_t aAddr[2], bAddr[4];
#pragma unroll
    for (int mt = 0; mt < 2; mt++)
        aAddr[mt] = sAsh + (uint32_t)((((grp>>1)*SLAB_STRIDE) + wm*32 + mt*16 + (grp&1)*8 + li) * 16);
#pragma unroll
    for (int p = 0; p < 4; p++)
        bAddr[p] = sBsh + (uint32_t)((((grp&1)*SLAB_STRIDE) + wn*64 + p*16 + (grp>>1)*8 + li) * 16);

#pragma unroll
    for (int seg = 0; seg < 3; seg++) {
        const __half* Aseg = (seg == 0) ? A0 : (seg == 1) ? A1 : A2;  // compile-time
        const __half* G = half ? (Bw + colBase * (long)K + seg*Ec)
                               : (Aseg + rowBase * (long)Ec);

        auto issueTile = [&](int kt, int buf) {
#pragma unroll
            for (int i = 0; i < 4; i++)
                cpa16ca(dstBase + (uint32_t)((buf*BUF_U4 + kq*SLAB_STRIDE + r0 + 32*i) * 16),
                        G + (long)(r0 + 32*i) * gstride + kt + kq*8);
            CPA_COMMIT();
        };

        __syncthreads();    // previous segment's readers done with both buffers
        issueTile(0, 0);
        int cur = 0;
        for (int ti = 0; ti < 16; ti++) {
            CPA_WAIT0();
            __syncthreads();
            if (ti + 1 < 16) issueTile((ti + 1) << 5, cur ^ 1);

            const uint32_t off = (uint32_t)(cur * BUF_U4 * 16);
#pragma unroll
            for (int s = 0; s < 2; s++) {
                const uint32_t soff = off + (uint32_t)(s * 2 * SLAB_STRIDE * 16);
                uint32_t af[2][4];
                uint32_t bf[8][2];
                ldsm_x4(af[0][0], af[0][1], af[0][2], af[0][3], aAddr[0] + soff);
                ldsm_x4(af[1][0], af[1][1], af[1][2], af[1][3], aAddr[1] + soff);
#pragma unroll
                for (int p = 0; p < 4; p++)
                    ldsm_x4(bf[2*p][0], bf[2*p][1], bf[2*p+1][0], bf[2*p+1][1], bAddr[p] + soff);
#pragma unroll
                for (int mt = 0; mt < 2; mt++)
#pragma unroll
                    for (int nt = 0; nt < 8; nt++)
                        mma_f16(acc[mt][nt], af[mt], bf[nt]);
            }
            cur ^= 1;
        }
    }

    const int c2 = (lane & 3) * 2;
    const int q  = lane >> 2;
#pragma unroll
    for (int mt = 0; mt < 2; mt++) {
        long r0o = rowBase + wm*32 + mt*16 + q;
        long r1o = r0o + 8;
#pragma unroll
        for (int nt = 0; nt < 8; nt++) {
            int col = (int)colBase + wn*64 + nt*8 + c2;
            float b0 = bias[col], b1 = bias[col+1];
            float4 a = acc[mt][nt];
            *reinterpret_cast<__half2*>(C16 + r0o * N + col) =
                __floats2half2_rn(apply_epi(a.x + b0, 1), apply_epi(a.y + b1, 1));
            *reinterpret_cast<__half2*>(C16 + r1o * N + col) =
                __floats2half2_rn(apply_epi(a.z + b0, 1), apply_epi(a.w + b1, 1));
        }
    }
}

// ---------------- local windowed attention: one warp per (token, head) -----
__global__ __launch_bounds__(256) void local_attn_kernel(const int* __restrict__ pad)
{
    int gwarp = (blockIdx.x * blockDim.x + threadIdx.x) >> 5;
    int lane  = threadIdx.x & 31;
    if (gwarp >= Nt * Hc) return;
    int h = gwarp % Hc;
    int n = gwarp / Hc;      // b*S + q
    int b = n / Sc, q = n % Sc;

    const __half* base = h_qkv + (long)n * (3*Ec);
    float2 qv = __half22float2(*reinterpret_cast<const __half2*>(base + h*HDc + lane*2));

    float sc[4]; bool val[4];
#pragma unroll
    for (int w = 0; w < 4; w++) {
        int kpos = q - 3 + w;
        bool v = (kpos >= 0) && (pad[b*Sc + kpos] == 0);
        float s = 0.f;
        if (v) {
            float2 kv = __half22float2(*reinterpret_cast<const __half2*>(
                h_qkv + ((long)(b*Sc + kpos)) * (3*Ec) + Ec + h*HDc + lane*2));
            s = qv.x*kv.x + qv.y*kv.y;
        }
#pragma unroll
        for (int o = 16; o > 0; o >>= 1) s += __shfl_xor_sync(0xffffffffu, s, o);
        sc[w]  = s * 0.125f;
        val[w] = v;
    }
    float m = -INFINITY;
#pragma unroll
    for (int w = 0; w < 4; w++) if (val[w]) m = fmaxf(m, sc[w]);
    float e[4]; float den = 0.f;
#pragma unroll
    for (int w = 0; w < 4; w++) { e[w] = val[w] ? expf(sc[w] - m) : 0.f; den += e[w]; }

    float2 o = make_float2(0.f, 0.f);
    if (den > 0.f) {
        float inv = 1.f / den;
#pragma unroll
        for (int w = 0; w < 4; w++) {
            if (!val[w]) continue;
            int kpos = q - 3 + w;
            float a = e[w] * inv;
            float2 vv = __half22float2(*reinterpret_cast<const __half2*>(
                h_qkv + ((long)(b*Sc + kpos)) * (3*Ec) + 2*Ec + h*HDc + lane*2));
            o.x += a * vv.x; o.y += a * vv.y;
        }
    }
    *reinterpret_cast<__half2*>(h_lo + (long)n*Ec + h*HDc + lane*2) =
        __floats2half2_rn(o.x, o.y);
}

// ---------------- valid length per batch ------------------------------------
__global__ void valid_len_kernel(const int* __restrict__ pad)
{
    int b = blockIdx.x;
    __shared__ int cnt;
    if (threadIdx.x == 0) cnt = 0;
    __syncthreads();
    int c = 0;
    for (int s = threadIdx.x; s < Sc; s += blockDim.x) c += (pad[b*Sc + s] != 0);
    atomicAdd(&cnt, c);
    __syncthreads();
    if (threadIdx.x == 0) {
        int v = Sc - cnt;
        g_vl[b] = v < 1 ? 1 : v;
    }
}

// ---------------- sampled positions: 32 lanes per token ---------------------
__global__ void sample_kernel()
{
    int idx = blockIdx.x * blockDim.x + threadIdx.x;
    int n = idx >> 5, p = idx & 31;
    if (n >= Nt) return;
    int b = n / Sc, s = n % Sc;

    float off = 0.f;
#pragma unroll
    for (int h = 0; h < Hc; h++) off += g_offraw[(long)n*(Hc*Pc) + h*Pc + p];

    float pos    = (float)s;
    float delta  = (0.9f - 0.1f) / 31.0f;
    float anchor = (p == 31) ? 0.9f : fmaf((float)p, delta, 0.1f);
    float samp   = anchor * pos + off;
    float lob    = fmaxf(pos - 256.f, 0.f);
    samp = fminf(fmaxf(samp, lob), pos);
    samp = fminf(samp, (float)(g_vl[b] - 1));
    g_sp[(long)n*Pc + p] = (int)rintf(samp);   // round-half-to-even == jnp.round
}

// ---------------- long deformable attention: one block per token ------------
__global__ __launch_bounds__(256) void long_attn_kernel(const int* __restrict__ pad)
{
    int n = blockIdx.x;            // token index
    int b = n / Sc, q = n % Sc;
    int tid = threadIdx.x, lane = tid & 31, warp = tid >> 5;

    __shared__ float s_sc[Pc];
    __shared__ float s_a[Pc];
    __shared__ int   s_j[Pc];
    if (tid < Pc) s_j[tid] = g_sp[(long)n*Pc + tid];
    __syncthreads();

    const __half* qrow = h_qkvd + (long)n * 1536;          // dq block
    uint4 q0 = *reinterpret_cast<const uint4*>(qrow + lane*16);
    uint4 q1 = *reinterpret_cast<const uint4*>(qrow + lane*16 + 8);

#pragma unroll
    for (int i = 0; i < 4; i++) {
        int p = warp*4 + i;
        int j = s_j[p];
        const __half* krow = h_qkvd + ((long)b*Sc + j) * 1536 + 512;  // dk block
        uint4 k0 = *reinterpret_cast<const uint4*>(krow + lane*16);
        uint4 k1 = *reinterpret_cast<const uint4*>(krow + lane*16 + 8);
        float s = dot8h(q0, k0) + dot8h(q1, k1);
#pragma unroll
        for (int o = 16; o > 0; o >>= 1) s += __shfl_xor_sync(0xffffffffu, s, o);
        if (lane == 0) s_sc[p] = s;
    }
    __syncthreads();

    if (tid < Pc) {
        int p = tid;
        int j = s_j[p];
        int rb = q - 3; if (rb < 0) rb = 0;
        bool inv = (pad[b*Sc + j] != 0) || (j > q) || (j >= rb);
        float sc = inv ? -INFINITY : (s_sc[p] / 22.627416997969520780827019587355f);
        float m = sc;
#pragma unroll
        for (int o = 16; o > 0; o >>= 1) m = fmaxf(m, __shfl_xor_sync(0xffffffffu, m, o));
        float e = inv ? 0.f : expf(sc - m);
        float den = e;
#pragma unroll
        for (int o = 16; o > 0; o >>= 1) den += __shfl_xor_sync(0xffffffffu, den, o);
        s_a[p] = (den > 0.f) ? (e / den) : 0.f;
    }
    __syncthreads();

    int d = tid * 2;
    float a0 = 0.f, a1 = 0.f;
    for (int p = 0; p < Pc; p++) {
        float a = s_a[p];
        if (a != 0.f) {
            float2 vv = __half22float2(*reinterpret_cast<const __half2*>(
                h_qkvd + ((long)b*Sc + s_j[p]) * 1536 + 1024 + d));     // dv block
            a0 += a * vv.x; a1 += a * vv.y;
        }
    }
    *reinterpret_cast<__half2*>(h_lattn + (long)n*Ec + d) = __floats2half2_rn(a0, a1);
}

// ---------------- block reduction helper -------------------------------------
__device__ __forceinline__ float block_sum_256(float v)
{
    __shared__ float sh[8];
    int lane = threadIdx.x & 31, w = threadIdx.x >> 5;
#pragma unroll
    for (int o = 16; o > 0; o >>= 1) v += __shfl_xor_sync(0xffffffffu, v, o);
    if (lane == 0) sh[w] = v;
    __syncthreads();
    float r = (lane < 8) ? sh[lane] : 0.f;
    if (w == 0) {
#pragma unroll
        for (int o = 4; o > 0; o >>= 1) r += __shfl_xor_sync(0xffffffffu, r, o);
        if (lane == 0) sh[0] = r;
    }
    __syncthreads();
    float out = sh[0];
    __syncthreads();
    return out;
}

// ---------------- gate fuse + residual + LN1 --------------------------------
__global__ __launch_bounds__(256) void fuse_ln1_kernel(
    const float* __restrict__ x, const float* __restrict__ gW, const float* __restrict__ bW)
{
    int n = blockIdx.x, tid = threadIdx.x;
    long base = (long)n*Ec + tid*2;
    float2 gg = __half22float2(*reinterpret_cast<const __half2*>(h_gate + base));
    float2 lc = __half22float2(*reinterpret_cast<const __half2*>(h_local + base));
    float2 lg = __half22float2(*reinterpret_cast<const __half2*>(h_long + base));
    float2 xx = *reinterpret_cast<const float2*>(x + base);
    float v0 = xx.x + gg.x*lc.x + (1.f - gg.x)*lg.x;
    float v1 = xx.y + gg.y*lc.y + (1.f - gg.y)*lg.y;

    float mean = block_sum_256(v0 + v1) * (1.f/512.f);
    float d0 = v0 - mean, d1 = v1 - mean;
    float var = block_sum_256(d0*d0 + d1*d1) * (1.f/512.f);
    float inv = 1.f / sqrtf(var + 1e-5f);

    int c = tid*2;
    float2 go = *reinterpret_cast<const float2*>(gW + c);
    float2 bo = *reinterpret_cast<const float2*>(bW + c);
    float o0 = d0*inv*go.x + bo.x;
    float o1 = d1*inv*go.y + bo.y;
    *reinterpret_cast<float2*>(g_x1 + base) = make_float2(o0, o1);
    *reinterpret_cast<__half2*>(h_x1 + base) = __floats2half2_rn(o0, o1);
}

// ---------------- residual + LN2 (final output) ------------------------------
__global__ __launch_bounds__(256) void ln2_kernel(
    const float* __restrict__ gW, const float* __restrict__ bW, float* __restrict__ out)
{
    int n = blockIdx.x, tid = threadIdx.x;
    long base = (long)n*Ec + tid*2;
    float2 xa = *reinterpret_cast<const float2*>(g_x1 + base);
    float2 fa = __half22float2(*reinterpret_cast<const __half2*>(h_f + base));
    float v0 = xa.x + fa.x, v1 = xa.y + fa.y;

    float mean = block_sum_256(v0 + v1) * (1.f/512.f);
    float d0 = v0 - mean, d1 = v1 - mean;
    float var = block_sum_256(d0*d0 + d1*d1) * (1.f/512.f);
    float inv = 1.f / sqrtf(var + 1e-5f);

    int c = tid*2;
    float2 go = *reinterpret_cast<const float2*>(gW + c);
    float2 bo = *reinterpret_cast<const float2*>(bW + c);
    *reinterpret_cast<float2*>(out + base) =
        make_float2(d0*inv*go.x + bo.x, d1*inv*go.y + bo.y);
}

// ---------------- host launcher ----------------------------------------------
template<typename T>
static T* sym(const void* s) { void* p = nullptr; cudaGetSymbolAddress(&p, s); return (T*)p; }

extern "C" void kernel_launch(void* const* d_in, const int* in_sizes, int n_in,
                              void* d_out, int out_size)
{
    const float* x    = (const float*)d_in[0];
    const int*   pad  = (const int*)d_in[1];          // bool mask delivered as int32
    const float* in_proj_w = (const float*)d_in[2];
    const float* in_proj_b = (const float*)d_in[3];
    const float* mha_out_w = (const float*)d_in[4];
    const float* mha_out_b = (const float*)d_in[5];
    const float* dq_w = (const float*)d_in[6];
    const float* dq_b = (const float*)d_in[7];
    const float* dk_w = (const float*)d_in[8];
    const float* dk_b = (const float*)d_in[9];
    const float* dv_w = (const float*)d_in[10];
    const float* dv_b = (const float*)d_in[11];
    const float* do_w = (const float*)d_in[12];
    const float* do_b = (const float*)d_in[13];
    const float* off1_w = (const float*)d_in[14];
    const float* off1_b = (const float*)d_in[15];
    const float* off2_w = (const float*)d_in[16];
    const float* off2_b = (const float*)d_in[17];
    const float* gate1_w = (const float*)d_in[18];
    const float* gate1_b = (const float*)d_in[19];
    const float* gate2_w = (const float*)d_in[20];
    const float* gate2_b = (const float*)d_in[21];
    const float* n1_g = (const float*)d_in[22];
    const float* n1_b = (const float*)d_in[23];
    const float* n2_g = (const float*)d_in[24];
    const float* n2_b = (const float*)d_in[25];
    const float* ffn1_w = (const float*)d_in[26];
    const float* ffn1_b = (const float*)d_in[27];
    const float* ffn2_w = (const float*)d_in[28];
    const float* ffn2_b = (const float*)d_in[29];

    float*  p_offr  = sym<float>(g_offraw);
    float*  p_bqkv  = sym<float>(g_bqkv);
    __half* ph_x    = sym<__half>(h_x);
    __half* ph_w    = sym<__half>(h_w);
    __half* ph_qkv  = sym<__half>(h_qkv);
    __half* ph_lo   = sym<__half>(h_lo);
    __half* ph_local= sym<__half>(h_local);
    __half* ph_long = sym<__half>(h_long);
    __half* ph_h1   = sym<__half>(h_h1);
    __half* ph_qkvd = sym<__half>(h_qkvd);
    __half* ph_latt = sym<__half>(h_lattn);
    __half* ph_gh   = sym<__half>(h_gh);
    __half* ph_gate = sym<__half>(h_gate);
    __half* ph_x1   = sym<__half>(h_x1);
    __half* ph_ffnh = sym<__half>(h_ffnh);
    __half* ph_f    = sym<__half>(h_f);

    dim3 blk(256);

    // 0) conversions
    cvt_all_kernel<<<9600, blk>>>(x, in_proj_w, mha_out_w, dq_w, dk_w, dv_w, do_w,
                                  off1_w, off2_w, gate1_w, gate2_w, ffn1_w, ffn2_w);
    pack_bias_kernel<<<6, blk>>>(dq_b, dk_b, dv_b);
    valid_len_kernel<<<Bc, blk>>>(pad);

    // 1) qkv = x @ in_proj_w^T + b   [8192,1536]
    hgemm<0,1><<<dim3(1536/128, Nt/128), blk>>>(ph_x, ph_w + W_INPROJ, in_proj_b, nullptr, ph_qkv, Nt, 1536, Ec);
    // 2) local windowed attention -> h_lo
    local_attn_kernel<<<(Nt*Hc)/8, blk>>>(pad);
    // 3) local_out
    hgemm<0,1><<<dim3(Ec/128, Nt/128), blk>>>(ph_lo, ph_w + W_MHA, mha_out_b, nullptr, ph_local, Nt, Ec, Ec);
    // 4) offset path
    hgemm<1,1><<<dim3(Ec/128, Nt/128), blk>>>(ph_x, ph_w + W_OFF1, off1_b, nullptr, ph_h1, Nt, Ec, Ec);
    hgemm<2,0><<<dim3(256/128, Nt/128), blk>>>(ph_h1, ph_w + W_OFF2, off2_b, p_offr, nullptr, Nt, 256, Ec);
    sample_kernel<<<(Nt*Pc)/256, blk>>>();
    // 5) packed dq|dk|dv projection: one N=1536 GEMM
    hgemm<0,1><<<dim3(1536/128, Nt/128), blk>>>(ph_x, ph_w + W_DQ, p_bqkv, nullptr, ph_qkvd, Nt, 1536, Ec);
    // 6) long attention -> h_lattn
    long_attn_kernel<<<Nt, blk>>>(pad);
    // 7) long_out
    hgemm<0,1><<<dim3(Ec/128, Nt/128), blk>>>(ph_latt, ph_w + W_DO, do_b, nullptr, ph_long, Nt, Ec, Ec);
    // 8) gate
    hgemm_gate1<<<dim3(Ec/128, Nt/128), blk>>>(ph_x, ph_local, ph_long, ph_w + W_GATE1, gate1_b, ph_gh);
    hgemm<3,1><<<dim3(Ec/128, Nt/128), blk>>>(ph_gh, ph_w + W_GATE2, gate2_b, nullptr, ph_gate, Nt, Ec, Ec);
    // 9) fuse + residual + LN1
    fuse_ln1_kernel<<<Nt, blk>>>(x, n1_g, n1_b);
    // 10) FFN
    hgemm<1,1><<<dim3(HIDc/128, Nt/128), blk>>>(ph_x1, ph_w + W_FFN1, ffn1_b, nullptr, ph_ffnh, Nt, HIDc, Ec);
    hgemm<0,1><<<dim3(Ec/128, Nt/128), blk>>>(ph_ffnh, ph_w + W_FFN2, ffn2_b, nullptr, ph_f, Nt, Ec, HIDc);
    // 11) residual + LN2 -> output
    ln2_kernel<<<Nt, blk>>>(n2_g, n2_b, (float*)d_out);
}

// round 15
// speedup vs baseline: 1.0826x; 1.0826x over previous
#include <cuda_runtime.h>
#include <cuda_fp16.h>
#include <math.h>
#include <stdint.h>

// Problem constants
#define Bc   8
#define Sc   1024
#define Ec   512
#define Hc   8
#define HDc  64
#define Pc   32
#define Nt   (Bc*Sc)     // 8192 tokens
#define HIDc 2048

// ---------------- scratch (device globals; allocation-free) ----------------
__device__ float g_offraw[Nt*Hc*Pc];   // fp32: feeds index rounding
__device__ float g_x1[Nt*Ec];          // fp32: dominant residual for LN2
__device__ float g_b3584[3584];        // packed inproj|dq|dk|dv|off1 bias
__device__ int   g_sp[Nt*Pc];
__device__ int   g_vl[Bc];

// fp16 activation/operand buffers
#define WTOT 5636096
__device__ __half h_x[Nt*Ec];
__device__ __half h_w[WTOT];
__device__ __half h_qkv[Nt*3*Ec];
__device__ __half h_lo[Nt*Ec];
__device__ __half h_local[Nt*Ec];
__device__ __half h_long[Nt*Ec];
__device__ __half h_h1[Nt*Ec];
__device__ __half h_qkvd[Nt*3*Ec];     // dq|dk|dv packed, stride 1536
__device__ __half h_lattn[Nt*Ec];
__device__ __half h_gh[Nt*Ec];
__device__ __half h_gate[Nt*Ec];
__device__ __half h_x1[Nt*Ec];
__device__ __half h_ffnh[Nt*HIDc];
__device__ __half h_f[Nt*Ec];

// weight offsets in h_w (halves); INPROJ|DQ|DK|DV|OFF1 contiguous = [3584,512]
#define W_INPROJ 0
#define W_DQ     786432
#define W_DK     1048576
#define W_DV     1310720
#define W_OFF1   1572864
#define W_MHA    1835008
#define W_DO     2097152
#define W_OFF2   2359296
#define W_GATE1  2490368
#define W_GATE2  3276800
#define W_FFN1   3538944
#define W_FFN2   4587520

// smem: ktile32, 4 slabs/buffer, slab stride 130 uint4 (conflict-free)
#define SLAB_STRIDE 130
#define BUF_U4      (4*SLAB_STRIDE)   // 520 uint4 per matrix per buffer

// ---------------- helpers -----------------------------------------------------
__device__ __forceinline__ void mma_f16(float4& d, const uint32_t* a, const uint32_t* b) {
    asm volatile(
        "mma.sync.aligned.m16n8k16.row.col.f32.f16.f16.f32 "
        "{%0,%1,%2,%3}, {%4,%5,%6,%7}, {%8,%9}, {%0,%1,%2,%3};"
        : "+f"(d.x), "+f"(d.y), "+f"(d.z), "+f"(d.w)
        : "r"(a[0]), "r"(a[1]), "r"(a[2]), "r"(a[3]),
          "r"(b[0]), "r"(b[1]));
}

__device__ __forceinline__ void ldsm_x4(uint32_t& r0, uint32_t& r1, uint32_t& r2, uint32_t& r3, uint32_t a) {
    asm volatile("ldmatrix.sync.aligned.m8n8.x4.shared.b16 {%0,%1,%2,%3}, [%4];"
        : "=r"(r0), "=r"(r1), "=r"(r2), "=r"(r3) : "r"(a));
}

__device__ __forceinline__ float apply_epi(float v, int EPI) {
    if (EPI == 1)      return 0.5f * v * (1.f + erff(v * 0.70710678118654752f));
    else if (EPI == 2) return tanhf(v);
    else if (EPI == 3) return 1.f / (1.f + expf(-v));
    return v;
}

__device__ __forceinline__ float dot8h(uint4 a, uint4 b) {
    const __half2* pa = reinterpret_cast<const __half2*>(&a);
    const __half2* pb = reinterpret_cast<const __half2*>(&b);
    float s = 0.f;
#pragma unroll
    for (int i = 0; i < 4; i++) {
        float2 fa = __half22float2(pa[i]);
        float2 fb = __half22float2(pb[i]);
        s += fa.x*fb.x + fa.y*fb.y;
    }
    return s;
}

// ---------------- fp32 -> fp16 conversion (x + 13 weights, one launch) --------
__global__ void cvt_all_kernel(
    const float* x,
    const float* w_inproj, const float* w_mha,
    const float* w_dq, const float* w_dk, const float* w_dv, const float* w_do,
    const float* w_off1, const float* w_off2,
    const float* w_gate1, const float* w_gate2,
    const float* w_ffn1, const float* w_ffn2)
{
    int g = blockIdx.x * blockDim.x + threadIdx.x;   // float4 index
    const float* src; __half* dst; int li;
    if      (g < 1048576) { src = x;        dst = h_x;            li = g;           }
    else if (g < 1245184) { src = w_inproj; dst = h_w + W_INPROJ; li = g - 1048576; }
    else if (g < 1310720) { src = w_dq;     dst = h_w + W_DQ;     li = g - 1245184; }
    else if (g < 1376256) { src = w_dk;     dst = h_w + W_DK;     li = g - 1310720; }
    else if (g < 1441792) { src = w_dv;     dst = h_w + W_DV;     li = g - 1376256; }
    else if (g < 1507328) { src = w_off1;   dst = h_w + W_OFF1;   li = g - 1441792; }
    else if (g < 1572864) { src = w_mha;    dst = h_w + W_MHA;    li = g - 1507328; }
    else if (g < 1638400) { src = w_do;     dst = h_w + W_DO;     li = g - 1572864; }
    else if (g < 1671168) { src = w_off2;   dst = h_w + W_OFF2;   li = g - 1638400; }
    else if (g < 1867776) { src = w_gate1;  dst = h_w + W_GATE1;  li = g - 1671168; }
    else if (g < 1933312) { src = w_gate2;  dst = h_w + W_GATE2;  li = g - 1867776; }
    else if (g < 2195456) { src = w_ffn1;   dst = h_w + W_FFN1;   li = g - 1933312; }
    else                  { src = w_ffn2;   dst = h_w + W_FFN2;   li = g - 2195456; }

    float4 v = reinterpret_cast<const float4*>(src)[li];
    __half2 h0 = __floats2half2_rn(v.x, v.y);
    __half2 h1 = __floats2half2_rn(v.z, v.w);
    uint2 out = make_uint2(*reinterpret_cast<uint32_t*>(&h0), *reinterpret_cast<uint32_t*>(&h1));
    reinterpret_cast<uint2*>(dst)[li] = out;
}

// pack inproj|dq|dk|dv|off1 biases into one 3584 vector
__global__ void pack_bias_kernel(const float* in_b, const float* dq_b,
                                 const float* dk_b, const float* dv_b,
                                 const float* o1_b)
{
    int i = blockIdx.x * blockDim.x + threadIdx.x;
    if (i >= 3584) return;
    float v;
    if      (i < 1536) v = in_b[i];
    else if (i < 2048) v = dq_b[i - 1536];
    else if (i < 2560) v = dk_b[i - 2048];
    else if (i < 3072) v = dv_b[i - 2560];
    else               v = o1_b[i - 3072];
    g_b3584[i] = v;
}

// ============================================================================
// Shared mainloop macro pieces (R13 register-staged double buffer + ldmatrix).
// ============================================================================
#define GEMM_PROLOG()                                                          \
    __shared__ uint4 sA[2*BUF_U4];                                             \
    __shared__ uint4 sB[2*BUF_U4];                                             \
    const int t    = threadIdx.x;                                              \
    const int lane = t & 31;                                                   \
    const int w    = t >> 5;                                                   \
    const int wm   = w & 3;                                                    \
    const int wn   = w >> 2;                                                   \
    float4 acc[2][8];                                                          \
    _Pragma("unroll")                                                          \
    for (int mt = 0; mt < 2; mt++)                                             \
        _Pragma("unroll")                                                      \
        for (int nt = 0; nt < 8; nt++) acc[mt][nt] = make_float4(0.f,0.f,0.f,0.f); \
    const int half = t >> 7;                                                   \
    const int tt   = t & 127;                                                  \
    const int kq   = tt & 3;                                                   \
    const int r0   = tt >> 2;                                                  \
    uint4* sDst = half ? sB : sA;                                              \
    const uint32_t sAsh = (uint32_t)__cvta_generic_to_shared(sA);              \
    const uint32_t sBsh = (uint32_t)__cvta_generic_to_shared(sB);              \
    const int li  = lane & 7;                                                  \
    const int grp = lane >> 3;                                                 \
    uint32_t aAddr[2], bAddr[4];                                               \
    _Pragma("unroll")                                                          \
    for (int mt = 0; mt < 2; mt++)                                             \
        aAddr[mt] = sAsh + (uint32_t)((((grp>>1)*SLAB_STRIDE) + wm*32 + mt*16 + (grp&1)*8 + li) * 16); \
    _Pragma("unroll")                                                          \
    for (int p = 0; p < 4; p++)                                                \
        bAddr[p] = sBsh + (uint32_t)((((grp&1)*SLAB_STRIDE) + wn*64 + p*16 + (grp>>1)*8 + li) * 16);

#define GEMM_MMA_PHASE(curbuf)                                                 \
    {                                                                          \
        const uint32_t off = (uint32_t)((curbuf) * BUF_U4 * 16);               \
        _Pragma("unroll")                                                      \
        for (int s = 0; s < 2; s++) {                                          \
            const uint32_t soff = off + (uint32_t)(s * 2 * SLAB_STRIDE * 16);  \
            uint32_t af[2][4];                                                 \
            uint32_t bf[8][2];                                                 \
            ldsm_x4(af[0][0], af[0][1], af[0][2], af[0][3], aAddr[0] + soff);  \
            ldsm_x4(af[1][0], af[1][1], af[1][2], af[1][3], aAddr[1] + soff);  \
            _Pragma("unroll")                                                  \
            for (int p = 0; p < 4; p++)                                        \
                ldsm_x4(bf[2*p][0], bf[2*p][1], bf[2*p+1][0], bf[2*p+1][1], bAddr[p] + soff); \
            _Pragma("unroll")                                                  \
            for (int mt = 0; mt < 2; mt++)                                     \
                _Pragma("unroll")                                              \
                for (int nt = 0; nt < 8; nt++)                                 \
                    mma_f16(acc[mt][nt], af[mt], bf[nt]);                      \
        }                                                                      \
    }

// ============================================================================
// Generic FP16 GEMM (R13 mainloop). EPI 0..3; OUT 0 fp32, 1 fp16.
// ============================================================================
template<int EPI, int OUT>
__global__ __launch_bounds__(256, 2) void hgemm(
    const __half* __restrict__ A, const __half* __restrict__ Bw,
    const float* __restrict__ bias, float* __restrict__ C32,
    __half* __restrict__ C16, int M, int N, int K)
{
    GEMM_PROLOG();
    const long rowBase = (long)blockIdx.y * 128;
    const long colBase = (long)blockIdx.x * 128;
    const __half* G = half ? (Bw + colBase * (long)K) : (A + rowBase * (long)K);

    uint4 st[4];
    auto ldgTile = [&](int kt) {
#pragma unroll
        for (int i = 0; i < 4; i++)
            st[i] = *reinterpret_cast<const uint4*>(G + (long)(r0 + 32*i) * K + kt + kq*8);
    };
    auto stsTile = [&](int buf) {
#pragma unroll
        for (int i = 0; i < 4; i++)
            sDst[buf*BUF_U4 + kq*SLAB_STRIDE + r0 + 32*i] = st[i];
    };

    ldgTile(0);
    stsTile(0);
    __syncthreads();

    const int nT = K >> 5;
    int cur = 0;
    for (int ti = 0; ti < nT; ti++) {
        const bool nxt = (ti + 1) < nT;
        if (nxt) ldgTile((ti + 1) << 5);
        GEMM_MMA_PHASE(cur);
        if (nxt) {
            __syncthreads();
            stsTile(cur ^ 1);
            __syncthreads();
            cur ^= 1;
        }
    }

    const int c2 = (lane & 3) * 2;
    const int q  = lane >> 2;
#pragma unroll
    for (int mt = 0; mt < 2; mt++) {
        long r0o = rowBase + wm*32 + mt*16 + q;
        long r1o = r0o + 8;
#pragma unroll
        for (int nt = 0; nt < 8; nt++) {
            int col = (int)colBase + wn*64 + nt*8 + c2;
            float b0 = bias[col], b1 = bias[col+1];
            float4 a = acc[mt][nt];
            float v0 = apply_epi(a.x + b0, EPI);
            float v1 = apply_epi(a.y + b1, EPI);
            float v2 = apply_epi(a.z + b0, EPI);
            float v3 = apply_epi(a.w + b1, EPI);
            if (OUT == 0) {
                *reinterpret_cast<float2*>(C32 + r0o * N + col) = make_float2(v0, v1);
                *reinterpret_cast<float2*>(C32 + r1o * N + col) = make_float2(v2, v3);
            } else {
                *reinterpret_cast<__half2*>(C16 + r0o * N + col) = __floats2half2_rn(v0, v1);
                *reinterpret_cast<__half2*>(C16 + r1o * N + col) = __floats2half2_rn(v2, v3);
            }
        }
    }
}

// ============================================================================
// Mega projection GEMM: C = x @ [inproj|dq|dk|dv|off1]^T, N=3584, K=512.
// Column segment routes output buffer + epilogue (uniform per CTA).
// ============================================================================
__global__ __launch_bounds__(256, 2) void hgemm_mega(const __half* __restrict__ A)
{
    GEMM_PROLOG();
    const int  K = 512;
    const long rowBase = (long)blockIdx.y * 128;
    const long colBase = (long)blockIdx.x * 128;
    const __half* Bw = h_w;   // contiguous [3584,512]
    const __half* G = half ? (Bw + colBase * (long)K) : (A + rowBase * (long)K);

    uint4 st[4];
    auto ldgTile = [&](int kt) {
#pragma unroll
        for (int i = 0; i < 4; i++)
            st[i] = *reinterpret_cast<const uint4*>(G + (long)(r0 + 32*i) * K + kt + kq*8);
    };
    auto stsTile = [&](int buf) {
#pragma unroll
        for (int i = 0; i < 4; i++)
            sDst[buf*BUF_U4 + kq*SLAB_STRIDE + r0 + 32*i] = st[i];
    };

    ldgTile(0);
    stsTile(0);
    __syncthreads();

    int cur = 0;
    for (int ti = 0; ti < 16; ti++) {
        const bool nxt = ti < 15;
        if (nxt) ldgTile((ti + 1) << 5);
        GEMM_MMA_PHASE(cur);
        if (nxt) {
            __syncthreads();
            stsTile(cur ^ 1);
            __syncthreads();
            cur ^= 1;
        }
    }

    // uniform per-CTA routing
    const int cb = (int)colBase;
    __half* Cd; int Nd; int colOff; int epi;
    if (cb < 1536)      { Cd = h_qkv;  Nd = 1536; colOff = cb;        epi = 0; }
    else if (cb < 3072) { Cd = h_qkvd; Nd = 1536; colOff = cb - 1536; epi = 0; }
    else                { Cd = h_h1;   Nd = 512;  colOff = cb - 3072; epi = 1; }

    const int c2 = (lane & 3) * 2;
    const int q  = lane >> 2;
#pragma unroll
    for (int mt = 0; mt < 2; mt++) {
        long r0o = rowBase + wm*32 + mt*16 + q;
        long r1o = r0o + 8;
#pragma unroll
        for (int nt = 0; nt < 8; nt++) {
            int colg = cb + wn*64 + nt*8 + c2;
            int col  = colOff + wn*64 + nt*8 + c2;
            float b0 = g_b3584[colg], b1 = g_b3584[colg+1];
            float4 a = acc[mt][nt];
            *reinterpret_cast<__half2*>(Cd + r0o * Nd + col) =
                __floats2half2_rn(apply_epi(a.x + b0, epi), apply_epi(a.y + b1, epi));
            *reinterpret_cast<__half2*>(Cd + r1o * Nd + col) =
                __floats2half2_rn(apply_epi(a.z + b0, epi), apply_epi(a.w + b1, epi));
        }
    }
}

// ============================================================================
// Merged output projections: blockIdx.x<4 -> local_out = lo@Wmha;
// else -> long_out = lattn@Wdo. N=512, K=512, uniform pointer selection.
// ============================================================================
__global__ __launch_bounds__(256, 2) void hgemm_proj(
    const float* __restrict__ mha_b, const float* __restrict__ do_b)
{
    GEMM_PROLOG();
    const int  N = 512, K = 512;
    const bool sel = (blockIdx.x >= 4);
    const __half* A  = sel ? h_lattn : h_lo;
    const __half* Bw = h_w + (sel ? W_DO : W_MHA);
    const float*  bias = sel ? do_b : mha_b;
    __half* C16 = sel ? h_long : h_local;
    const long rowBase = (long)blockIdx.y * 128;
    const long colBase = (long)(blockIdx.x & 3) * 128;
    const __half* G = half ? (Bw + colBase * (long)K) : (A + rowBase * (long)K);

    uint4 st[4];
    auto ldgTile = [&](int kt) {
#pragma unroll
        for (int i = 0; i < 4; i++)
            st[i] = *reinterpret_cast<const uint4*>(G + (long)(r0 + 32*i) * K + kt + kq*8);
    };
    auto stsTile = [&](int buf) {
#pragma unroll
        for (int i = 0; i < 4; i++)
            sDst[buf*BUF_U4 + kq*SLAB_STRIDE + r0 + 32*i] = st[i];
    };

    ldgTile(0);
    stsTile(0);
    __syncthreads();

    int cur = 0;
    for (int ti = 0; ti < 16; ti++) {
        const bool nxt = ti < 15;
        if (nxt) ldgTile((ti + 1) << 5);
        GEMM_MMA_PHASE(cur);
        if (nxt) {
            __syncthreads();
            stsTile(cur ^ 1);
            __syncthreads();
            cur ^= 1;
        }
    }

    const int c2 = (lane & 3) * 2;
    const int q  = lane >> 2;
#pragma unroll
    for (int mt = 0; mt < 2; mt++) {
        long r0o = rowBase + wm*32 + mt*16 + q;
        long r1o = r0o + 8;
#pragma unroll
        for (int nt = 0; nt < 8; nt++) {
            int col = (int)colBase + wn*64 + nt*8 + c2;
            float b0 = bias[col], b1 = bias[col+1];
            float4 a = acc[mt][nt];
            *reinterpret_cast<__half2*>(C16 + r0o * N + col) =
                __floats2half2_rn(a.x + b0, a.y + b1);
            *reinterpret_cast<__half2*>(C16 + r1o * N + col) =
                __floats2half2_rn(a.z + b0, a.w + b1);
        }
    }
}

// ============================================================================
// gate1-specialized fp16 GEMM (R13 mainloop per segment)
// ============================================================================
__global__ __launch_bounds__(256, 2) void hgemm_gate1(
    const __half* __restrict__ A0, const __half* __restrict__ A1,
    const __half* __restrict__ A2, const __half* __restrict__ Bw,
    const float* __restrict__ bias, __half* __restrict__ C16)
{
    GEMM_PROLOG();
    const int  N = 512, K = 1536;
    const long rowBase = (long)blockIdx.y * 128;
    const long colBase = (long)blockIdx.x * 128;
    const long gstride = half ? (long)K : (long)Ec;
    uint4 st[4];

#pragma unroll
    for (int seg = 0; seg < 3; seg++) {
        const __half* Aseg = (seg == 0) ? A0 : (seg == 1) ? A1 : A2;  // compile-time
        const __half* G = half ? (Bw + colBase * (long)K + seg*Ec)
                               : (Aseg + rowBase * (long)Ec);

        auto ldgTile = [&](int kt) {
#pragma unroll
            for (int i = 0; i < 4; i++)
                st[i] = *reinterpret_cast<const uint4*>(G + (long)(r0 + 32*i) * gstride + kt + kq*8);
        };
        auto stsTile = [&](int buf) {
#pragma unroll
            for (int i = 0; i < 4; i++)
                sDst[buf*BUF_U4 + kq*SLAB_STRIDE + r0 + 32*i] = st[i];
        };

        __syncthreads();
        ldgTile(0);
        stsTile(0);
        __syncthreads();

        int cur = 0;
        for (int ti = 0; ti < 16; ti++) {
            const bool nxt = ti < 15;
            if (nxt) ldgTile((ti + 1) << 5);
            GEMM_MMA_PHASE(cur);
            if (nxt) {
                __syncthreads();
                stsTile(cur ^ 1);
                __syncthreads();
                cur ^= 1;
            }
        }
    }

    const int c2 = (lane & 3) * 2;
    const int q  = lane >> 2;
#pragma unroll
    for (int mt = 0; mt < 2; mt++) {
        long r0o = rowBase + wm*32 + mt*16 + q;
        long r1o = r0o + 8;
#pragma unroll
        for (int nt = 0; nt < 8; nt++) {
            int col = (int)colBase + wn*64 + nt*8 + c2;
            float b0 = bias[col], b1 = bias[col+1];
            float4 a = acc[mt][nt];
            *reinterpret_cast<__half2*>(C16 + r0o * N + col) =
                __floats2half2_rn(apply_epi(a.x + b0, 1), apply_epi(a.y + b1, 1));
            *reinterpret_cast<__half2*>(C16 + r1o * N + col) =
                __floats2half2_rn(apply_epi(a.z + b0, 1), apply_epi(a.w + b1, 1));
        }
    }
}

// ---------------- local windowed attention: one warp per (token, head) -----
__global__ __launch_bounds__(256) void local_attn_kernel(const int* __restrict__ pad)
{
    int gwarp = (blockIdx.x * blockDim.x + threadIdx.x) >> 5;
    int lane  = threadIdx.x & 31;
    if (gwarp >= Nt * Hc) return;
    int h = gwarp % Hc;
    int n = gwarp / Hc;
    int b = n / Sc, q = n % Sc;

    const __half* base = h_qkv + (long)n * (3*Ec);
    float2 qv = __half22float2(*reinterpret_cast<const __half2*>(base + h*HDc + lane*2));

    float sc[4]; bool val[4];
#pragma unroll
    for (int w = 0; w < 4; w++) {
        int kpos = q - 3 + w;
        bool v = (kpos >= 0) && (pad[b*Sc + kpos] == 0);
        float s = 0.f;
        if (v) {
            float2 kv = __half22float2(*reinterpret_cast<const __half2*>(
                h_qkv + ((long)(b*Sc + kpos)) * (3*Ec) + Ec + h*HDc + lane*2));
            s = qv.x*kv.x + qv.y*kv.y;
        }
#pragma unroll
        for (int o = 16; o > 0; o >>= 1) s += __shfl_xor_sync(0xffffffffu, s, o);
        sc[w]  = s * 0.125f;
        val[w] = v;
    }
    float m = -INFINITY;
#pragma unroll
    for (int w = 0; w < 4; w++) if (val[w]) m = fmaxf(m, sc[w]);
    float e[4]; float den = 0.f;
#pragma unroll
    for (int w = 0; w < 4; w++) { e[w] = val[w] ? expf(sc[w] - m) : 0.f; den += e[w]; }

    float2 o = make_float2(0.f, 0.f);
    if (den > 0.f) {
        float inv = 1.f / den;
#pragma unroll
        for (int w = 0; w < 4; w++) {
            if (!val[w]) continue;
            int kpos = q - 3 + w;
            float a = e[w] * inv;
            float2 vv = __half22float2(*reinterpret_cast<const __half2*>(
                h_qkv + ((long)(b*Sc + kpos)) * (3*Ec) + 2*Ec + h*HDc + lane*2));
            o.x += a * vv.x; o.y += a * vv.y;
        }
    }
    *reinterpret_cast<__half2*>(h_lo + (long)n*Ec + h*HDc + lane*2) =
        __floats2half2_rn(o.x, o.y);
}

// ---------------- valid length per batch ------------------------------------
__global__ void valid_len_kernel(const int* __restrict__ pad)
{
    int b = blockIdx.x;
    __shared__ int cnt;
    if (threadIdx.x == 0) cnt = 0;
    __syncthreads();
    int c = 0;
    for (int s = threadIdx.x; s < Sc; s += blockDim.x) c += (pad[b*Sc + s] != 0);
    atomicAdd(&cnt, c);
    __syncthreads();
    if (threadIdx.x == 0) {
        int v = Sc - cnt;
        g_vl[b] = v < 1 ? 1 : v;
    }
}

// ---------------- sampled positions: 32 lanes per token ---------------------
__global__ void sample_kernel()
{
    int idx = blockIdx.x * blockDim.x + threadIdx.x;
    int n = idx >> 5, p = idx & 31;
    if (n >= Nt) return;
    int b = n / Sc, s = n % Sc;

    float off = 0.f;
#pragma unroll
    for (int h = 0; h < Hc; h++) off += g_offraw[(long)n*(Hc*Pc) + h*Pc + p];

    float pos    = (float)s;
    float delta  = (0.9f - 0.1f) / 31.0f;
    float anchor = (p == 31) ? 0.9f : fmaf((float)p, delta, 0.1f);
    float samp   = anchor * pos + off;
    float lob    = fmaxf(pos - 256.f, 0.f);
    samp = fminf(fmaxf(samp, lob), pos);
    samp = fminf(samp, (float)(g_vl[b] - 1));
    g_sp[(long)n*Pc + p] = (int)rintf(samp);   // round-half-to-even == jnp.round
}

// ---------------- long deformable attention: one block per token ------------
__global__ __launch_bounds__(256) void long_attn_kernel(const int* __restrict__ pad)
{
    int n = blockIdx.x;
    int b = n / Sc, q = n % Sc;
    int tid = threadIdx.x, lane = tid & 31, warp = tid >> 5;

    __shared__ float s_sc[Pc];
    __shared__ float s_a[Pc];
    __shared__ int   s_j[Pc];
    if (tid < Pc) s_j[tid] = g_sp[(long)n*Pc + tid];
    __syncthreads();

    const __half* qrow = h_qkvd + (long)n * 1536;          // dq block
    uint4 q0 = *reinterpret_cast<const uint4*>(qrow + lane*16);
    uint4 q1 = *reinterpret_cast<const uint4*>(qrow + lane*16 + 8);

#pragma unroll
    for (int i = 0; i < 4; i++) {
        int p = warp*4 + i;
        int j = s_j[p];
        const __half* krow = h_qkvd + ((long)b*Sc + j) * 1536 + 512;  // dk block
        uint4 k0 = *reinterpret_cast<const uint4*>(krow + lane*16);
        uint4 k1 = *reinterpret_cast<const uint4*>(krow + lane*16 + 8);
        float s = dot8h(q0, k0) + dot8h(q1, k1);
#pragma unroll
        for (int o = 16; o > 0; o >>= 1) s += __shfl_xor_sync(0xffffffffu, s, o);
        if (lane == 0) s_sc[p] = s;
    }
    __syncthreads();

    if (tid < Pc) {
        int p = tid;
        int j = s_j[p];
        int rb = q - 3; if (rb < 0) rb = 0;
        bool inv = (pad[b*Sc + j] != 0) || (j > q) || (j >= rb);
        float sc = inv ? -INFINITY : (s_sc[p] / 22.627416997969520780827019587355f);
        float m = sc;
#pragma unroll
        for (int o = 16; o > 0; o >>= 1) m = fmaxf(m, __shfl_xor_sync(0xffffffffu, m, o));
        float e = inv ? 0.f : expf(sc - m);
        float den = e;
#pragma unroll
        for (int o = 16; o > 0; o >>= 1) den += __shfl_xor_sync(0xffffffffu, den, o);
        s_a[p] = (den > 0.f) ? (e / den) : 0.f;
    }
    __syncthreads();

    int d = tid * 2;
    float a0 = 0.f, a1 = 0.f;
    for (int p = 0; p < Pc; p++) {
        float a = s_a[p];
        if (a != 0.f) {
            float2 vv = __half22float2(*reinterpret_cast<const __half2*>(
                h_qkvd + ((long)b*Sc + s_j[p]) * 1536 + 1024 + d));     // dv block
            a0 += a * vv.x; a1 += a * vv.y;
        }
    }
    *reinterpret_cast<__half2*>(h_lattn + (long)n*Ec + d) = __floats2half2_rn(a0, a1);
}

// ---------------- block reduction helper -------------------------------------
__device__ __forceinline__ float block_sum_256(float v)
{
    __shared__ float sh[8];
    int lane = threadIdx.x & 31, w = threadIdx.x >> 5;
#pragma unroll
    for (int o = 16; o > 0; o >>= 1) v += __shfl_xor_sync(0xffffffffu, v, o);
    if (lane == 0) sh[w] = v;
    __syncthreads();
    float r = (lane < 8) ? sh[lane] : 0.f;
    if (w == 0) {
#pragma unroll
        for (int o = 4; o > 0; o >>= 1) r += __shfl_xor_sync(0xffffffffu, r, o);
        if (lane == 0) sh[0] = r;
    }
    __syncthreads();
    float out = sh[0];
    __syncthreads();
    return out;
}

// ---------------- gate fuse + residual + LN1 --------------------------------
__global__ __launch_bounds__(256) void fuse_ln1_kernel(
    const float* __restrict__ x, const float* __restrict__ gW, const float* __restrict__ bW)
{
    int n = blockIdx.x, tid = threadIdx.x;
    long base = (long)n*Ec + tid*2;
    float2 gg = __half22float2(*reinterpret_cast<const __half2*>(h_gate + base));
    float2 lc = __half22float2(*reinterpret_cast<const __half2*>(h_local + base));
    float2 lg = __half22float2(*reinterpret_cast<const __half2*>(h_long + base));
    float2 xx = *reinterpret_cast<const float2*>(x + base);
    float v0 = xx.x + gg.x*lc.x + (1.f - gg.x)*lg.x;
    float v1 = xx.y + gg.y*lc.y + (1.f - gg.y)*lg.y;

    float mean = block_sum_256(v0 + v1) * (1.f/512.f);
    float d0 = v0 - mean, d1 = v1 - mean;
    float var = block_sum_256(d0*d0 + d1*d1) * (1.f/512.f);
    float inv = 1.f / sqrtf(var + 1e-5f);

    int c = tid*2;
    float2 go = *reinterpret_cast<const float2*>(gW + c);
    float2 bo = *reinterpret_cast<const float2*>(bW + c);
    float o0 = d0*inv*go.x + bo.x;
    float o1 = d1*inv*go.y + bo.y;
    *reinterpret_cast<float2*>(g_x1 + base) = make_float2(o0, o1);
    *reinterpret_cast<__half2*>(h_x1 + base) = __floats2half2_rn(o0, o1);
}

// ---------------- residual + LN2 (final output) ------------------------------
__global__ __launch_bounds__(256) void ln2_kernel(
    const float* __restrict__ gW, const float* __restrict__ bW, float* __restrict__ out)
{
    int n = blockIdx.x, tid = threadIdx.x;
    long base = (long)n*Ec + tid*2;
    float2 xa = *reinterpret_cast<const float2*>(g_x1 + base);
    float2 fa = __half22float2(*reinterpret_cast<const __half2*>(h_f + base));
    float v0 = xa.x + fa.x, v1 = xa.y + fa.y;

    float mean = block_sum_256(v0 + v1) * (1.f/512.f);
    float d0 = v0 - mean, d1 = v1 - mean;
    float var = block_sum_256(d0*d0 + d1*d1) * (1.f/512.f);
    float inv = 1.f / sqrtf(var + 1e-5f);

    int c = tid*2;
    float2 go = *reinterpret_cast<const float2*>(gW + c);
    float2 bo = *reinterpret_cast<const float2*>(bW + c);
    *reinterpret_cast<float2*>(out + base) =
        make_float2(d0*inv*go.x + bo.x, d1*inv*go.y + bo.y);
}

// ---------------- host launcher ----------------------------------------------
template<typename T>
static T* sym(const void* s) { void* p = nullptr; cudaGetSymbolAddress(&p, s); return (T*)p; }

extern "C" void kernel_launch(void* const* d_in, const int* in_sizes, int n_in,
                              void* d_out, int out_size)
{
    const float* x    = (const float*)d_in[0];
    const int*   pad  = (const int*)d_in[1];          // bool mask delivered as int32
    const float* in_proj_w = (const float*)d_in[2];
    const float* in_proj_b = (const float*)d_in[3];
    const float* mha_out_w = (const float*)d_in[4];
    const float* mha_out_b = (const float*)d_in[5];
    const float* dq_w = (const float*)d_in[6];
    const float* dq_b = (const float*)d_in[7];
    const float* dk_w = (const float*)d_in[8];
    const float* dk_b = (const float*)d_in[9];
    const float* dv_w = (const float*)d_in[10];
    const float* dv_b = (const float*)d_in[11];
    const float* do_w = (const float*)d_in[12];
    const float* do_b = (const float*)d_in[13];
    const float* off1_w = (const float*)d_in[14];
    const float* off1_b = (const float*)d_in[15];
    const float* off2_w = (const float*)d_in[16];
    const float* off2_b = (const float*)d_in[17];
    const float* gate1_w = (const float*)d_in[18];
    const float* gate1_b = (const float*)d_in[19];
    const float* gate2_w = (const float*)d_in[20];
    const float* gate2_b = (const float*)d_in[21];
    const float* n1_g = (const float*)d_in[22];
    const float* n1_b = (const float*)d_in[23];
    const float* n2_g = (const float*)d_in[24];
    const float* n2_b = (const float*)d_in[25];
    const float* ffn1_w = (const float*)d_in[26];
    const float* ffn1_b = (const float*)d_in[27];
    const float* ffn2_w = (const float*)d_in[28];
    const float* ffn2_b = (const float*)d_in[29];

    float*  p_offr  = sym<float>(g_offraw);
    __half* ph_x    = sym<__half>(h_x);
    __half* ph_w    = sym<__half>(h_w);
    __half* ph_h1   = sym<__half>(h_h1);
    __half* ph_local= sym<__half>(h_local);
    __half* ph_long = sym<__half>(h_long);
    __half* ph_gh   = sym<__half>(h_gh);
    __half* ph_gate = sym<__half>(h_gate);
    __half* ph_x1   = sym<__half>(h_x1);
    __half* ph_ffnh = sym<__half>(h_ffnh);
    __half* ph_f    = sym<__half>(h_f);

    dim3 blk(256);

    // 0) conversions
    cvt_all_kernel<<<9600, blk>>>(x, in_proj_w, mha_out_w, dq_w, dk_w, dv_w, do_w,
                                  off1_w, off2_w, gate1_w, gate2_w, ffn1_w, ffn2_w);
    pack_bias_kernel<<<14, blk>>>(in_proj_b, dq_b, dk_b, dv_b, off1_b);
    valid_len_kernel<<<Bc, blk>>>(pad);

    // 1) mega projection: qkv | dqkv | h1(gelu) in one launch
    hgemm_mega<<<dim3(3584/128, Nt/128), blk>>>(ph_x);
    // 2) local windowed attention -> h_lo
    local_attn_kernel<<<(Nt*Hc)/8, blk>>>(pad);
    // 3) offsets + sampling
    hgemm<2,0><<<dim3(256/128, Nt/128), blk>>>(ph_h1, ph_w + W_OFF2, off2_b, p_offr, nullptr, Nt, 256, Ec);
    sample_kernel<<<(Nt*Pc)/256, blk>>>();
    // 4) long attention -> h_lattn
    long_attn_kernel<<<Nt, blk>>>(pad);
    // 5) merged output projections (mha_out | do)
    hgemm_proj<<<dim3(8, Nt/128), blk>>>(mha_out_b, do_b);
    // 6) gate
    hgemm_gate1<<<dim3(Ec/128, Nt/128), blk>>>(ph_x, ph_local, ph_long, ph_w + W_GATE1, gate1_b, ph_gh);
    hgemm<3,1><<<dim3(Ec/128, Nt/128), blk>>>(ph_gh, ph_w + W_GATE2, gate2_b, nullptr, ph_gate, Nt, Ec, Ec);
    // 7) fuse + residual + LN1
    fuse_ln1_kernel<<<Nt, blk>>>(x, n1_g, n1_b);
    // 8) FFN
    hgemm<1,1><<<dim3(HIDc/128, Nt/128), blk>>>(ph_x1, ph_w + W_FFN1, ffn1_b, nullptr, ph_ffnh, Nt, HIDc, Ec);
    hgemm<0,1><<<dim3(Ec/128, Nt/128), blk>>>(ph_ffnh, ph_w + W_FFN2, ffn2_b, nullptr, ph_f, Nt, Ec, HIDc);
    // 9) LN2 -> output
    ln2_kernel<<<Nt, blk>>>(n2_g, n2_b, (float*)d_out);
}

// round 16
// speedup vs baseline: 1.1063x; 1.0218x over previous
#include <cuda_runtime.h>
#include <cuda_fp16.h>
#include <math.h>
#include <stdint.h>

// Problem constants
#define Bc   8
#define Sc   1024
#define Ec   512
#define Hc   8
#define HDc  64
#define Pc   32
#define Nt   (Bc*Sc)     // 8192 tokens
#define HIDc 2048

// ---------------- scratch (device globals; allocation-free) ----------------
__device__ float g_offraw[Nt*Hc*Pc];   // fp32: feeds index rounding
__device__ float g_x1[Nt*Ec];          // fp32: dominant residual for LN2
__device__ float g_b3584[3584];        // packed inproj|dq|dk|dv|off1 bias
__device__ int   g_sp[Nt*Pc];
__device__ int   g_vl[Bc];

// fp16 activation/operand buffers
#define WTOT 5636096
__device__ __half h_x[Nt*Ec];
__device__ __half h_w[WTOT];
__device__ __half h_qkv[Nt*3*Ec];
__device__ __half h_lo[Nt*Ec];
__device__ __half h_local[Nt*Ec];
__device__ __half h_long[Nt*Ec];
__device__ __half h_h1[Nt*Ec];
__device__ __half h_qkvd[Nt*3*Ec];     // dq|dk|dv packed, stride 1536
__device__ __half h_lattn[Nt*Ec];
__device__ __half h_gh[Nt*Ec];
__device__ __half h_gate[Nt*Ec];
__device__ __half h_x1[Nt*Ec];
__device__ __half h_ffnh[Nt*HIDc];
__device__ __half h_f[Nt*Ec];

// weight offsets in h_w (halves); INPROJ|DQ|DK|DV|OFF1 contiguous = [3584,512]
#define W_INPROJ 0
#define W_DQ     786432
#define W_DK     1048576
#define W_DV     1310720
#define W_OFF1   1572864
#define W_MHA    1835008
#define W_DO     2097152
#define W_OFF2   2359296
#define W_GATE1  2490368
#define W_GATE2  3276800
#define W_FFN1   3538944
#define W_FFN2   4587520

// smem: ktile32, 4 slabs/buffer, slab stride 130 uint4 (conflict-free)
#define SLAB_STRIDE 130
#define BUF_U4      (4*SLAB_STRIDE)   // 520 uint4 per matrix per buffer

// ---------------- helpers -----------------------------------------------------
__device__ __forceinline__ void mma_f16(float4& d, const uint32_t* a, const uint32_t* b) {
    asm volatile(
        "mma.sync.aligned.m16n8k16.row.col.f32.f16.f16.f32 "
        "{%0,%1,%2,%3}, {%4,%5,%6,%7}, {%8,%9}, {%0,%1,%2,%3};"
        : "+f"(d.x), "+f"(d.y), "+f"(d.z), "+f"(d.w)
        : "r"(a[0]), "r"(a[1]), "r"(a[2]), "r"(a[3]),
          "r"(b[0]), "r"(b[1]));
}

__device__ __forceinline__ void ldsm_x4(uint32_t& r0, uint32_t& r1, uint32_t& r2, uint32_t& r3, uint32_t a) {
    asm volatile("ldmatrix.sync.aligned.m8n8.x4.shared.b16 {%0,%1,%2,%3}, [%4];"
        : "=r"(r0), "=r"(r1), "=r"(r2), "=r"(r3) : "r"(a));
}

__device__ __forceinline__ float apply_epi(float v, int EPI) {
    if (EPI == 1)      return 0.5f * v * (1.f + erff(v * 0.70710678118654752f));
    else if (EPI == 2) return tanhf(v);
    else if (EPI == 3) return 1.f / (1.f + expf(-v));
    return v;
}

__device__ __forceinline__ float dot8h(uint4 a, uint4 b) {
    const __half2* pa = reinterpret_cast<const __half2*>(&a);
    const __half2* pb = reinterpret_cast<const __half2*>(&b);
    float s = 0.f;
#pragma unroll
    for (int i = 0; i < 4; i++) {
        float2 fa = __half22float2(pa[i]);
        float2 fb = __half22float2(pb[i]);
        s += fa.x*fb.x + fa.y*fb.y;
    }
    return s;
}

// ---------------- fp32 -> fp16 conversion (x + 13 weights, one launch) --------
__global__ void cvt_all_kernel(
    const float* x,
    const float* w_inproj, const float* w_mha,
    const float* w_dq, const float* w_dk, const float* w_dv, const float* w_do,
    const float* w_off1, const float* w_off2,
    const float* w_gate1, const float* w_gate2,
    const float* w_ffn1, const float* w_ffn2)
{
    int g = blockIdx.x * blockDim.x + threadIdx.x;   // float4 index
    const float* src; __half* dst; int li;
    if      (g < 1048576) { src = x;        dst = h_x;            li = g;           }
    else if (g < 1245184) { src = w_inproj; dst = h_w + W_INPROJ; li = g - 1048576; }
    else if (g < 1310720) { src = w_dq;     dst = h_w + W_DQ;     li = g - 1245184; }
    else if (g < 1376256) { src = w_dk;     dst = h_w + W_DK;     li = g - 1310720; }
    else if (g < 1441792) { src = w_dv;     dst = h_w + W_DV;     li = g - 1376256; }
    else if (g < 1507328) { src = w_off1;   dst = h_w + W_OFF1;   li = g - 1441792; }
    else if (g < 1572864) { src = w_mha;    dst = h_w + W_MHA;    li = g - 1507328; }
    else if (g < 1638400) { src = w_do;     dst = h_w + W_DO;     li = g - 1572864; }
    else if (g < 1671168) { src = w_off2;   dst = h_w + W_OFF2;   li = g - 1638400; }
    else if (g < 1867776) { src = w_gate1;  dst = h_w + W_GATE1;  li = g - 1671168; }
    else if (g < 1933312) { src = w_gate2;  dst = h_w + W_GATE2;  li = g - 1867776; }
    else if (g < 2195456) { src = w_ffn1;   dst = h_w + W_FFN1;   li = g - 1933312; }
    else                  { src = w_ffn2;   dst = h_w + W_FFN2;   li = g - 2195456; }

    float4 v = reinterpret_cast<const float4*>(src)[li];
    __half2 h0 = __floats2half2_rn(v.x, v.y);
    __half2 h1 = __floats2half2_rn(v.z, v.w);
    uint2 out = make_uint2(*reinterpret_cast<uint32_t*>(&h0), *reinterpret_cast<uint32_t*>(&h1));
    reinterpret_cast<uint2*>(dst)[li] = out;
}

// prep: blocks 0..13 pack bias (3584); blocks 14..21 valid_len per batch
__global__ void prep_kernel(const float* in_b, const float* dq_b,
                            const float* dk_b, const float* dv_b,
                            const float* o1_b, const int* __restrict__ pad)
{
    if (blockIdx.x < 14) {
        int i = blockIdx.x * blockDim.x + threadIdx.x;
        if (i >= 3584) return;
        float v;
        if      (i < 1536) v = in_b[i];
        else if (i < 2048) v = dq_b[i - 1536];
        else if (i < 2560) v = dk_b[i - 2048];
        else if (i < 3072) v = dv_b[i - 2560];
        else               v = o1_b[i - 3072];
        g_b3584[i] = v;
    } else {
        int b = blockIdx.x - 14;
        __shared__ int cnt;
        if (threadIdx.x == 0) cnt = 0;
        __syncthreads();
        int c = 0;
        for (int s = threadIdx.x; s < Sc; s += blockDim.x) c += (pad[b*Sc + s] != 0);
        atomicAdd(&cnt, c);
        __syncthreads();
        if (threadIdx.x == 0) {
            int v = Sc - cnt;
            g_vl[b] = v < 1 ? 1 : v;
        }
    }
}

// ============================================================================
// Shared mainloop macro pieces (R13 register-staged double buffer + ldmatrix).
// ============================================================================
#define GEMM_PROLOG()                                                          \
    __shared__ uint4 sA[2*BUF_U4];                                             \
    __shared__ uint4 sB[2*BUF_U4];                                             \
    const int t    = threadIdx.x;                                              \
    const int lane = t & 31;                                                   \
    const int w    = t >> 5;                                                   \
    const int wm   = w & 3;                                                    \
    const int wn   = w >> 2;                                                   \
    float4 acc[2][8];                                                          \
    _Pragma("unroll")                                                          \
    for (int mt = 0; mt < 2; mt++)                                             \
        _Pragma("unroll")                                                      \
        for (int nt = 0; nt < 8; nt++) acc[mt][nt] = make_float4(0.f,0.f,0.f,0.f); \
    const int half = t >> 7;                                                   \
    const int tt   = t & 127;                                                  \
    const int kq   = tt & 3;                                                   \
    const int r0   = tt >> 2;                                                  \
    uint4* sDst = half ? sB : sA;                                              \
    const uint32_t sAsh = (uint32_t)__cvta_generic_to_shared(sA);              \
    const uint32_t sBsh = (uint32_t)__cvta_generic_to_shared(sB);              \
    const int li  = lane & 7;                                                  \
    const int grp = lane >> 3;                                                 \
    uint32_t aAddr[2], bAddr[4];                                               \
    _Pragma("unroll")                                                          \
    for (int mt = 0; mt < 2; mt++)                                             \
        aAddr[mt] = sAsh + (uint32_t)((((grp>>1)*SLAB_STRIDE) + wm*32 + mt*16 + (grp&1)*8 + li) * 16); \
    _Pragma("unroll")                                                          \
    for (int p = 0; p < 4; p++)                                                \
        bAddr[p] = sBsh + (uint32_t)((((grp&1)*SLAB_STRIDE) + wn*64 + p*16 + (grp>>1)*8 + li) * 16);

#define GEMM_MMA_PHASE(curbuf)                                                 \
    {                                                                          \
        const uint32_t off = (uint32_t)((curbuf) * BUF_U4 * 16);               \
        _Pragma("unroll")                                                      \
        for (int s = 0; s < 2; s++) {                                          \
            const uint32_t soff = off + (uint32_t)(s * 2 * SLAB_STRIDE * 16);  \
            uint32_t af[2][4];                                                 \
            uint32_t bf[8][2];                                                 \
            ldsm_x4(af[0][0], af[0][1], af[0][2], af[0][3], aAddr[0] + soff);  \
            ldsm_x4(af[1][0], af[1][1], af[1][2], af[1][3], aAddr[1] + soff);  \
            _Pragma("unroll")                                                  \
            for (int p = 0; p < 4; p++)                                        \
                ldsm_x4(bf[2*p][0], bf[2*p][1], bf[2*p+1][0], bf[2*p+1][1], bAddr[p] + soff); \
            _Pragma("unroll")                                                  \
            for (int mt = 0; mt < 2; mt++)                                     \
                _Pragma("unroll")                                              \
                for (int nt = 0; nt < 8; nt++)                                 \
                    mma_f16(acc[mt][nt], af[mt], bf[nt]);                      \
        }                                                                      \
    }

// ============================================================================
// Generic FP16 GEMM (R13 mainloop). EPI 0..3; OUT 0 fp32, 1 fp16.
// ============================================================================
template<int EPI, int OUT>
__global__ __launch_bounds__(256, 2) void hgemm(
    const __half* __restrict__ A, const __half* __restrict__ Bw,
    const float* __restrict__ bias, float* __restrict__ C32,
    __half* __restrict__ C16, int M, int N, int K)
{
    GEMM_PROLOG();
    const long rowBase = (long)blockIdx.y * 128;
    const long colBase = (long)blockIdx.x * 128;
    const __half* G = half ? (Bw + colBase * (long)K) : (A + rowBase * (long)K);

    uint4 st[4];
    auto ldgTile = [&](int kt) {
#pragma unroll
        for (int i = 0; i < 4; i++)
            st[i] = *reinterpret_cast<const uint4*>(G + (long)(r0 + 32*i) * K + kt + kq*8);
    };
    auto stsTile = [&](int buf) {
#pragma unroll
        for (int i = 0; i < 4; i++)
            sDst[buf*BUF_U4 + kq*SLAB_STRIDE + r0 + 32*i] = st[i];
    };

    ldgTile(0);
    stsTile(0);
    __syncthreads();

    const int nT = K >> 5;
    int cur = 0;
    for (int ti = 0; ti < nT; ti++) {
        const bool nxt = (ti + 1) < nT;
        if (nxt) ldgTile((ti + 1) << 5);
        GEMM_MMA_PHASE(cur);
        if (nxt) {
            __syncthreads();
            stsTile(cur ^ 1);
            __syncthreads();
            cur ^= 1;
        }
    }

    const int c2 = (lane & 3) * 2;
    const int q  = lane >> 2;
#pragma unroll
    for (int mt = 0; mt < 2; mt++) {
        long r0o = rowBase + wm*32 + mt*16 + q;
        long r1o = r0o + 8;
#pragma unroll
        for (int nt = 0; nt < 8; nt++) {
            int col = (int)colBase + wn*64 + nt*8 + c2;
            float b0 = bias[col], b1 = bias[col+1];
            float4 a = acc[mt][nt];
            float v0 = apply_epi(a.x + b0, EPI);
            float v1 = apply_epi(a.y + b1, EPI);
            float v2 = apply_epi(a.z + b0, EPI);
            float v3 = apply_epi(a.w + b1, EPI);
            if (OUT == 0) {
                *reinterpret_cast<float2*>(C32 + r0o * N + col) = make_float2(v0, v1);
                *reinterpret_cast<float2*>(C32 + r1o * N + col) = make_float2(v2, v3);
            } else {
                *reinterpret_cast<__half2*>(C16 + r0o * N + col) = __floats2half2_rn(v0, v1);
                *reinterpret_cast<__half2*>(C16 + r1o * N + col) = __floats2half2_rn(v2, v3);
            }
        }
    }
}

// ============================================================================
// Mega projection GEMM: C = x @ [inproj|dq|dk|dv|off1]^T, N=3584, K=512.
// ============================================================================
__global__ __launch_bounds__(256, 2) void hgemm_mega(const __half* __restrict__ A)
{
    GEMM_PROLOG();
    const int  K = 512;
    const long rowBase = (long)blockIdx.y * 128;
    const long colBase = (long)blockIdx.x * 128;
    const __half* Bw = h_w;
    const __half* G = half ? (Bw + colBase * (long)K) : (A + rowBase * (long)K);

    uint4 st[4];
    auto ldgTile = [&](int kt) {
#pragma unroll
        for (int i = 0; i < 4; i++)
            st[i] = *reinterpret_cast<const uint4*>(G + (long)(r0 + 32*i) * K + kt + kq*8);
    };
    auto stsTile = [&](int buf) {
#pragma unroll
        for (int i = 0; i < 4; i++)
            sDst[buf*BUF_U4 + kq*SLAB_STRIDE + r0 + 32*i] = st[i];
    };

    ldgTile(0);
    stsTile(0);
    __syncthreads();

    int cur = 0;
    for (int ti = 0; ti < 16; ti++) {
        const bool nxt = ti < 15;
        if (nxt) ldgTile((ti + 1) << 5);
        GEMM_MMA_PHASE(cur);
        if (nxt) {
            __syncthreads();
            stsTile(cur ^ 1);
            __syncthreads();
            cur ^= 1;
        }
    }

    const int cb = (int)colBase;
    __half* Cd; int Nd; int colOff; int epi;
    if (cb < 1536)      { Cd = h_qkv;  Nd = 1536; colOff = cb;        epi = 0; }
    else if (cb < 3072) { Cd = h_qkvd; Nd = 1536; colOff = cb - 1536; epi = 0; }
    else                { Cd = h_h1;   Nd = 512;  colOff = cb - 3072; epi = 1; }

    const int c2 = (lane & 3) * 2;
    const int q  = lane >> 2;
#pragma unroll
    for (int mt = 0; mt < 2; mt++) {
        long r0o = rowBase + wm*32 + mt*16 + q;
        long r1o = r0o + 8;
#pragma unroll
        for (int nt = 0; nt < 8; nt++) {
            int colg = cb + wn*64 + nt*8 + c2;
            int col  = colOff + wn*64 + nt*8 + c2;
            float b0 = g_b3584[colg], b1 = g_b3584[colg+1];
            float4 a = acc[mt][nt];
            *reinterpret_cast<__half2*>(Cd + r0o * Nd + col) =
                __floats2half2_rn(apply_epi(a.x + b0, epi), apply_epi(a.y + b1, epi));
            *reinterpret_cast<__half2*>(Cd + r1o * Nd + col) =
                __floats2half2_rn(apply_epi(a.z + b0, epi), apply_epi(a.w + b1, epi));
        }
    }
}

// ============================================================================
// Merged output projections: blockIdx.x<4 -> local_out; else long_out.
// ============================================================================
__global__ __launch_bounds__(256, 2) void hgemm_proj(
    const float* __restrict__ mha_b, const float* __restrict__ do_b)
{
    GEMM_PROLOG();
    const int  N = 512, K = 512;
    const bool sel = (blockIdx.x >= 4);
    const __half* A  = sel ? h_lattn : h_lo;
    const __half* Bw = h_w + (sel ? W_DO : W_MHA);
    const float*  bias = sel ? do_b : mha_b;
    __half* C16 = sel ? h_long : h_local;
    const long rowBase = (long)blockIdx.y * 128;
    const long colBase = (long)(blockIdx.x & 3) * 128;
    const __half* G = half ? (Bw + colBase * (long)K) : (A + rowBase * (long)K);

    uint4 st[4];
    auto ldgTile = [&](int kt) {
#pragma unroll
        for (int i = 0; i < 4; i++)
            st[i] = *reinterpret_cast<const uint4*>(G + (long)(r0 + 32*i) * K + kt + kq*8);
    };
    auto stsTile = [&](int buf) {
#pragma unroll
        for (int i = 0; i < 4; i++)
            sDst[buf*BUF_U4 + kq*SLAB_STRIDE + r0 + 32*i] = st[i];
    };

    ldgTile(0);
    stsTile(0);
    __syncthreads();

    int cur = 0;
    for (int ti = 0; ti < 16; ti++) {
        const bool nxt = ti < 15;
        if (nxt) ldgTile((ti + 1) << 5);
        GEMM_MMA_PHASE(cur);
        if (nxt) {
            __syncthreads();
            stsTile(cur ^ 1);
            __syncthreads();
            cur ^= 1;
        }
    }

    const int c2 = (lane & 3) * 2;
    const int q  = lane >> 2;
#pragma unroll
    for (int mt = 0; mt < 2; mt++) {
        long r0o = rowBase + wm*32 + mt*16 + q;
        long r1o = r0o + 8;
#pragma unroll
        for (int nt = 0; nt < 8; nt++) {
            int col = (int)colBase + wn*64 + nt*8 + c2;
            float b0 = bias[col], b1 = bias[col+1];
            float4 a = acc[mt][nt];
            *reinterpret_cast<__half2*>(C16 + r0o * N + col) =
                __floats2half2_rn(a.x + b0, a.y + b1);
            *reinterpret_cast<__half2*>(C16 + r1o * N + col) =
                __floats2half2_rn(a.z + b0, a.w + b1);
        }
    }
}

// ============================================================================
// gate1-specialized fp16 GEMM (R13 mainloop per segment)
// ============================================================================
__global__ __launch_bounds__(256, 2) void hgemm_gate1(
    const __half* __restrict__ A0, const __half* __restrict__ A1,
    const __half* __restrict__ A2, const __half* __restrict__ Bw,
    const float* __restrict__ bias, __half* __restrict__ C16)
{
    GEMM_PROLOG();
    const int  N = 512, K = 1536;
    const long rowBase = (long)blockIdx.y * 128;
    const long colBase = (long)blockIdx.x * 128;
    const long gstride = half ? (long)K : (long)Ec;
    uint4 st[4];

#pragma unroll
    for (int seg = 0; seg < 3; seg++) {
        const __half* Aseg = (seg == 0) ? A0 : (seg == 1) ? A1 : A2;  // compile-time
        const __half* G = half ? (Bw + colBase * (long)K + seg*Ec)
                               : (Aseg + rowBase * (long)Ec);

        auto ldgTile = [&](int kt) {
#pragma unroll
            for (int i = 0; i < 4; i++)
                st[i] = *reinterpret_cast<const uint4*>(G + (long)(r0 + 32*i) * gstride + kt + kq*8);
        };
        auto stsTile = [&](int buf) {
#pragma unroll
            for (int i = 0; i < 4; i++)
                sDst[buf*BUF_U4 + kq*SLAB_STRIDE + r0 + 32*i] = st[i];
        };

        __syncthreads();
        ldgTile(0);
        stsTile(0);
        __syncthreads();

        int cur = 0;
        for (int ti = 0; ti < 16; ti++) {
            const bool nxt = ti < 15;
            if (nxt) ldgTile((ti + 1) << 5);
            GEMM_MMA_PHASE(cur);
            if (nxt) {
                __syncthreads();
                stsTile(cur ^ 1);
                __syncthreads();
                cur ^= 1;
            }
        }
    }

    const int c2 = (lane & 3) * 2;
    const int q  = lane >> 2;
#pragma unroll
    for (int mt = 0; mt < 2; mt++) {
        long r0o = rowBase + wm*32 + mt*16 + q;
        long r1o = r0o + 8;
#pragma unroll
        for (int nt = 0; nt < 8; nt++) {
            int col = (int)colBase + wn*64 + nt*8 + c2;
            float b0 = bias[col], b1 = bias[col+1];
            float4 a = acc[mt][nt];
            *reinterpret_cast<__half2*>(C16 + r0o * N + col) =
                __floats2half2_rn(apply_epi(a.x + b0, 1), apply_epi(a.y + b1, 1));
            *reinterpret_cast<__half2*>(C16 + r1o * N + col) =
                __floats2half2_rn(apply_epi(a.z + b0, 1), apply_epi(a.w + b1, 1));
        }
    }
}

// ---------------- local windowed attention: one WARP per token --------------
// lane = 4*h + li ; per-lane dims = [lane*16, lane*16+16) => coalesced rows.
// Dot over head = 16 dims/lane reduced across the 4-lane group (xor 1, 2).
__global__ __launch_bounds__(256) void local_attn_kernel(const int* __restrict__ pad)
{
    int n = ((blockIdx.x * blockDim.x + threadIdx.x) >> 5);   // token
    int lane = threadIdx.x & 31;
    if (n >= Nt) return;
    int b = n / Sc, q = n % Sc;

    const __half* qrow = h_qkv + (long)n * 1536;
    uint4 q0 = *reinterpret_cast<const uint4*>(qrow + lane*16);
    uint4 q1 = *reinterpret_cast<const uint4*>(qrow + lane*16 + 8);

    float sc[4]; bool val[4];
#pragma unroll
    for (int w = 0; w < 4; w++) {
        int kpos = q - 3 + w;
        bool v = (kpos >= 0) && (pad[b*Sc + kpos] == 0);
        float s = 0.f;
        if (v) {
            const __half* krow = h_qkv + ((long)(b*Sc + kpos)) * 1536 + 512;
            uint4 k0 = *reinterpret_cast<const uint4*>(krow + lane*16);
            uint4 k1 = *reinterpret_cast<const uint4*>(krow + lane*16 + 8);
            s = dot8h(q0, k0) + dot8h(q1, k1);
        }
        s += __shfl_xor_sync(0xffffffffu, s, 1);
        s += __shfl_xor_sync(0xffffffffu, s, 2);
        sc[w]  = s * 0.125f;   // / sqrt(64)
        val[w] = v;
    }
    float m = -INFINITY;
#pragma unroll
    for (int w = 0; w < 4; w++) if (val[w]) m = fmaxf(m, sc[w]);
    float e[4]; float den = 0.f;
#pragma unroll
    for (int w = 0; w < 4; w++) { e[w] = val[w] ? expf(sc[w] - m) : 0.f; den += e[w]; }

    float o[16];
#pragma unroll
    for (int i = 0; i < 16; i++) o[i] = 0.f;
    if (den > 0.f) {
        float inv = 1.f / den;
#pragma unroll
        for (int w = 0; w < 4; w++) {
            if (!val[w]) continue;
            int kpos = q - 3 + w;
            float a = e[w] * inv;
            const __half* vrow = h_qkv + ((long)(b*Sc + kpos)) * 1536 + 1024;
            uint4 v0 = *reinterpret_cast<const uint4*>(vrow + lane*16);
            uint4 v1 = *reinterpret_cast<const uint4*>(vrow + lane*16 + 8);
            const __half2* pv0 = reinterpret_cast<const __half2*>(&v0);
            const __half2* pv1 = reinterpret_cast<const __half2*>(&v1);
#pragma unroll
            for (int i = 0; i < 4; i++) {
                float2 f0 = __half22float2(pv0[i]);
                float2 f1 = __half22float2(pv1[i]);
                o[2*i]   += a * f0.x;  o[2*i+1] += a * f0.y;
                o[8+2*i] += a * f1.x;  o[8+2*i+1] += a * f1.y;
            }
        }
    }
    __half2 ov[8];
#pragma unroll
    for (int i = 0; i < 8; i++) ov[i] = __floats2half2_rn(o[2*i], o[2*i+1]);
    uint4* dst = reinterpret_cast<uint4*>(h_lo + (long)n*Ec + lane*16);
    dst[0] = *reinterpret_cast<uint4*>(&ov[0]);
    dst[1] = *reinterpret_cast<uint4*>(&ov[4]);
}

// ---------------- sampled positions: 32 lanes per token ---------------------
__global__ void sample_kernel()
{
    int idx = blockIdx.x * blockDim.x + threadIdx.x;
    int n = idx >> 5, p = idx & 31;
    if (n >= Nt) return;
    int b = n / Sc, s = n % Sc;

    float off = 0.f;
#pragma unroll
    for (int h = 0; h < Hc; h++) off += g_offraw[(long)n*(Hc*Pc) + h*Pc + p];

    float pos    = (float)s;
    float delta  = (0.9f - 0.1f) / 31.0f;
    float anchor = (p == 31) ? 0.9f : fmaf((float)p, delta, 0.1f);
    float samp   = anchor * pos + off;
    float lob    = fmaxf(pos - 256.f, 0.f);
    samp = fminf(fmaxf(samp, lob), pos);
    samp = fminf(samp, (float)(g_vl[b] - 1));
    g_sp[(long)n*Pc + p] = (int)rintf(samp);   // round-half-to-even == jnp.round
}

// ---------------- long deformable attention: one block per token ------------
__global__ __launch_bounds__(256) void long_attn_kernel(const int* __restrict__ pad)
{
    int n = blockIdx.x;
    int b = n / Sc, q = n % Sc;
    int tid = threadIdx.x, lane = tid & 31, warp = tid >> 5;

    __shared__ float s_sc[Pc];
    __shared__ float s_a[Pc];
    __shared__ int   s_j[Pc];
    if (tid < Pc) s_j[tid] = g_sp[(long)n*Pc + tid];
    __syncthreads();

    const __half* qrow = h_qkvd + (long)n * 1536;          // dq block
    uint4 q0 = *reinterpret_cast<const uint4*>(qrow + lane*16);
    uint4 q1 = *reinterpret_cast<const uint4*>(qrow + lane*16 + 8);

#pragma unroll
    for (int i = 0; i < 4; i++) {
        int p = warp*4 + i;
        int j = s_j[p];
        const __half* krow = h_qkvd + ((long)b*Sc + j) * 1536 + 512;  // dk block
        uint4 k0 = *reinterpret_cast<const uint4*>(krow + lane*16);
        uint4 k1 = *reinterpret_cast<const uint4*>(krow + lane*16 + 8);
        float s = dot8h(q0, k0) + dot8h(q1, k1);
#pragma unroll
        for (int o = 16; o > 0; o >>= 1) s += __shfl_xor_sync(0xffffffffu, s, o);
        if (lane == 0) s_sc[p] = s;
    }
    __syncthreads();

    if (tid < Pc) {
        int p = tid;
        int j = s_j[p];
        int rb = q - 3; if (rb < 0) rb = 0;
        bool inv = (pad[b*Sc + j] != 0) || (j > q) || (j >= rb);
        float sc = inv ? -INFINITY : (s_sc[p] / 22.627416997969520780827019587355f);
        float m = sc;
#pragma unroll
        for (int o = 16; o > 0; o >>= 1) m = fmaxf(m, __shfl_xor_sync(0xffffffffu, m, o));
        float e = inv ? 0.f : expf(sc - m);
        float den = e;
#pragma unroll
        for (int o = 16; o > 0; o >>= 1) den += __shfl_xor_sync(0xffffffffu, den, o);
        s_a[p] = (den > 0.f) ? (e / den) : 0.f;
    }
    __syncthreads();

    int d = tid * 2;
    float a0 = 0.f, a1 = 0.f;
    for (int p = 0; p < Pc; p++) {
        float a = s_a[p];
        if (a != 0.f) {
            float2 vv = __half22float2(*reinterpret_cast<const __half2*>(
                h_qkvd + ((long)b*Sc + s_j[p]) * 1536 + 1024 + d));     // dv block
            a0 += a * vv.x; a1 += a * vv.y;
        }
    }
    *reinterpret_cast<__half2*>(h_lattn + (long)n*Ec + d) = __floats2half2_rn(a0, a1);
}

// ---------------- block reduction helper -------------------------------------
__device__ __forceinline__ float block_sum_256(float v)
{
    __shared__ float sh[8];
    int lane = threadIdx.x & 31, w = threadIdx.x >> 5;
#pragma unroll
    for (int o = 16; o > 0; o >>= 1) v += __shfl_xor_sync(0xffffffffu, v, o);
    if (lane == 0) sh[w] = v;
    __syncthreads();
    float r = (lane < 8) ? sh[lane] : 0.f;
    if (w == 0) {
#pragma unroll
        for (int o = 4; o > 0; o >>= 1) r += __shfl_xor_sync(0xffffffffu, r, o);
        if (lane == 0) sh[0] = r;
    }
    __syncthreads();
    float out = sh[0];
    __syncthreads();
    return out;
}

// ---------------- gate fuse + residual + LN1 --------------------------------
__global__ __launch_bounds__(256) void fuse_ln1_kernel(
    const float* __restrict__ x, const float* __restrict__ gW, const float* __restrict__ bW)
{
    int n = blockIdx.x, tid = threadIdx.x;
    long base = (long)n*Ec + tid*2;
    float2 gg = __half22float2(*reinterpret_cast<const __half2*>(h_gate + base));
    float2 lc = __half22float2(*reinterpret_cast<const __half2*>(h_local + base));
    float2 lg = __half22float2(*reinterpret_cast<const __half2*>(h_long + base));
    float2 xx = *reinterpret_cast<const float2*>(x + base);
    float v0 = xx.x + gg.x*lc.x + (1.f - gg.x)*lg.x;
    float v1 = xx.y + gg.y*lc.y + (1.f - gg.y)*lg.y;

    float mean = block_sum_256(v0 + v1) * (1.f/512.f);
    float d0 = v0 - mean, d1 = v1 - mean;
    float var = block_sum_256(d0*d0 + d1*d1) * (1.f/512.f);
    float inv = 1.f / sqrtf(var + 1e-5f);

    int c = tid*2;
    float2 go = *reinterpret_cast<const float2*>(gW + c);
    float2 bo = *reinterpret_cast<const float2*>(bW + c);
    float o0 = d0*inv*go.x + bo.x;
    float o1 = d1*inv*go.y + bo.y;
    *reinterpret_cast<float2*>(g_x1 + base) = make_float2(o0, o1);
    *reinterpret_cast<__half2*>(h_x1 + base) = __floats2half2_rn(o0, o1);
}

// ---------------- residual + LN2 (final output) ------------------------------
__global__ __launch_bounds__(256) void ln2_kernel(
    const float* __restrict__ gW, const float* __restrict__ bW, float* __restrict__ out)
{
    int n = blockIdx.x, tid = threadIdx.x;
    long base = (long)n*Ec + tid*2;
    float2 xa = *reinterpret_cast<const float2*>(g_x1 + base);
    float2 fa = __half22float2(*reinterpret_cast<const __half2*>(h_f + base));
    float v0 = xa.x + fa.x, v1 = xa.y + fa.y;

    float mean = block_sum_256(v0 + v1) * (1.f/512.f);
    float d0 = v0 - mean, d1 = v1 - mean;
    float var = block_sum_256(d0*d0 + d1*d1) * (1.f/512.f);
    float inv = 1.f / sqrtf(var + 1e-5f);

    int c = tid*2;
    float2 go = *reinterpret_cast<const float2*>(gW + c);
    float2 bo = *reinterpret_cast<const float2*>(bW + c);
    *reinterpret_cast<float2*>(out + base) =
        make_float2(d0*inv*go.x + bo.x, d1*inv*go.y + bo.y);
}

// ---------------- host launcher ----------------------------------------------
template<typename T>
static T* sym(const void* s) { void* p = nullptr; cudaGetSymbolAddress(&p, s); return (T*)p; }

extern "C" void kernel_launch(void* const* d_in, const int* in_sizes, int n_in,
                              void* d_out, int out_size)
{
    const float* x    = (const float*)d_in[0];
    const int*   pad  = (const int*)d_in[1];
    const float* in_proj_w = (const float*)d_in[2];
    const float* in_proj_b = (const float*)d_in[3];
    const float* mha_out_w = (const float*)d_in[4];
    const float* mha_out_b = (const float*)d_in[5];
    const float* dq_w = (const float*)d_in[6];
    const float* dq_b = (const float*)d_in[7];
    const float* dk_w = (const float*)d_in[8];
    const float* dk_b = (const float*)d_in[9];
    const float* dv_w = (const float*)d_in[10];
    const float* dv_b = (const float*)d_in[11];
    const float* do_w = (const float*)d_in[12];
    const float* do_b = (const float*)d_in[13];
    const float* off1_w = (const float*)d_in[14];
    const float* off1_b = (const float*)d_in[15];
    const float* off2_w = (const float*)d_in[16];
    const float* off2_b = (const float*)d_in[17];
    const float* gate1_w = (const float*)d_in[18];
    const float* gate1_b = (const float*)d_in[19];
    const float* gate2_w = (const float*)d_in[20];
    const float* gate2_b = (const float*)d_in[21];
    const float* n1_g = (const float*)d_in[22];
    const float* n1_b = (const float*)d_in[23];
    const float* n2_g = (const float*)d_in[24];
    const float* n2_b = (const float*)d_in[25];
    const float* ffn1_w = (const float*)d_in[26];
    const float* ffn1_b = (const float*)d_in[27];
    const float* ffn2_w = (const float*)d_in[28];
    const float* ffn2_b = (const float*)d_in[29];

    float*  p_offr  = sym<float>(g_offraw);
    __half* ph_x    = sym<__half>(h_x);
    __half* ph_w    = sym<__half>(h_w);
    __half* ph_h1   = sym<__half>(h_h1);
    __half* ph_local= sym<__half>(h_local);
    __half* ph_long = sym<__half>(h_long);
    __half* ph_gh   = sym<__half>(h_gh);
    __half* ph_gate = sym<__half>(h_gate);
    __half* ph_x1   = sym<__half>(h_x1);
    __half* ph_ffnh = sym<__half>(h_ffnh);
    __half* ph_f    = sym<__half>(h_f);

    dim3 blk(256);

    // 0) conversions + prep
    cvt_all_kernel<<<9600, blk>>>(x, in_proj_w, mha_out_w, dq_w, dk_w, dv_w, do_w,
                                  off1_w, off2_w, gate1_w, gate2_w, ffn1_w, ffn2_w);
    prep_kernel<<<22, blk>>>(in_proj_b, dq_b, dk_b, dv_b, off1_b, pad);

    // 1) mega projection: qkv | dqkv | h1(gelu) in one launch
    hgemm_mega<<<dim3(3584/128, Nt/128), blk>>>(ph_x);
    // 2) local windowed attention -> h_lo (one warp per token)
    local_attn_kernel<<<Nt/8, blk>>>(pad);
    // 3) offsets + sampling
    hgemm<2,0><<<dim3(256/128, Nt/128), blk>>>(ph_h1, ph_w + W_OFF2, off2_b, p_offr, nullptr, Nt, 256, Ec);
    sample_kernel<<<(Nt*Pc)/256, blk>>>();
    // 4) long attention -> h_lattn
    long_attn_kernel<<<Nt, blk>>>(pad);
    // 5) merged output projections (mha_out | do)
    hgemm_proj<<<dim3(8, Nt/128), blk>>>(mha_out_b, do_b);
    // 6) gate
    hgemm_gate1<<<dim3(Ec/128, Nt/128), blk>>>(ph_x, ph_local, ph_long, ph_w + W_GATE1, gate1_b, ph_gh);
    hgemm<3,1><<<dim3(Ec/128, Nt/128), blk>>>(ph_gh, ph_w + W_GATE2, gate2_b, nullptr, ph_gate, Nt, Ec, Ec);
    // 7) fuse + residual + LN1
    fuse_ln1_kernel<<<Nt, blk>>>(x, n1_g, n1_b);
    // 8) FFN
    hgemm<1,1><<<dim3(HIDc/128, Nt/128), blk>>>(ph_x1, ph_w + W_FFN1, ffn1_b, nullptr, ph_ffnh, Nt, HIDc, Ec);
    hgemm<0,1><<<dim3(Ec/128, Nt/128), blk>>>(ph_ffnh, ph_w + W_FFN2, ffn2_b, nullptr, ph_f, Nt, Ec, HIDc);
    // 9) LN2 -> output
    ln2_kernel<<<Nt, blk>>>(n2_g, n2_b, (float*)d_out);
}